// round 1
// baseline (speedup 1.0000x reference)
#include <cuda_runtime.h>
#include <cuda_bf16.h>
#include <cstdint>

// Problem constants
constexpr int B   = 32;
constexpr int DIM = 1024;
constexpr int MM  = 512;
constexpr int OUT_PER_B = DIM * (DIM + 1) / 2;   // 524800
constexpr float ALPHA = 0.4f;
constexpr float EPS   = 1e-5f;

// Scratch (static __device__ globals: allocation-guard safe)
__device__ float g_dcov[(size_t)B * DIM * DIM];   // 134 MB
__device__ float g_diag[B * DIM];
__device__ float g_mean[B * DIM];
__device__ float g_tot[B];

// ---------------------------------------------------------------------------
// K0: diag[b][i] = ||x_i||^2 / (2M)
// One warp per row; MM=512 floats = 128 float4 -> 4 float4 per lane.
// ---------------------------------------------------------------------------
__global__ void diag_kernel(const float* __restrict__ x) {
    int warp = (blockIdx.x * blockDim.x + threadIdx.x) >> 5;
    int lane = threadIdx.x & 31;
    if (warp >= B * DIM) return;
    const float4* row = reinterpret_cast<const float4*>(x + (size_t)warp * MM);
    float s = 0.f;
    #pragma unroll
    for (int k = 0; k < 4; k++) {
        float4 v = row[lane + 32 * k];
        s += v.x * v.x + v.y * v.y + v.z * v.z + v.w * v.w;
    }
    #pragma unroll
    for (int off = 16; off > 0; off >>= 1)
        s += __shfl_down_sync(0xFFFFFFFFu, s, off);
    if (lane == 0) g_diag[warp] = s * (1.f / (2.f * MM));
}

// ---------------------------------------------------------------------------
// K1: symmetric tiled SGEMM + fused dcov epilogue.
// Computes only upper-triangular 128x128 tiles (36 of 64), mirrors the store.
//   s      = <x_i, x_j> / (2M)
//   dcov   = (i==j) ? 0 : max(diag_i + diag_j - 2 s, 0)
//   out    = (dcov + EPS)^0.4
// ---------------------------------------------------------------------------
constexpr int BM = 128, BN = 128, BK = 16;
constexpr int NT = DIM / BM;              // 8 tiles per dim
constexpr int NPAIRS = NT * (NT + 1) / 2; // 36

__global__ __launch_bounds__(256, 2)
void gemm_dcov_kernel(const float* __restrict__ x) {
    // map blockIdx.x -> (bi, bj) with bi <= bj
    int p = blockIdx.x;
    int bi = 0;
    while (p >= NT - bi) { p -= NT - bi; bi++; }
    int bj = bi + p;
    int b = blockIdx.y;

    __shared__ float As[BK][BM + 4];
    __shared__ float Bs[BK][BN + 4];

    const float* Abase = x + ((size_t)b * DIM + bi * BM) * MM;
    const float* Bbase = x + ((size_t)b * DIM + bj * BN) * MM;

    int tid = threadIdx.x;
    int loadRow = tid >> 2;            // 0..63
    int loadCol = (tid & 3) * 4;       // 0,4,8,12
    int ty = tid >> 4;                 // 0..15
    int tx = tid & 15;                 // 0..15

    float acc[8][8] = {};

    for (int k0 = 0; k0 < MM; k0 += BK) {
        float4 a0 = *reinterpret_cast<const float4*>(Abase + (size_t)loadRow * MM + k0 + loadCol);
        float4 a1 = *reinterpret_cast<const float4*>(Abase + (size_t)(loadRow + 64) * MM + k0 + loadCol);
        float4 b0 = *reinterpret_cast<const float4*>(Bbase + (size_t)loadRow * MM + k0 + loadCol);
        float4 b1 = *reinterpret_cast<const float4*>(Bbase + (size_t)(loadRow + 64) * MM + k0 + loadCol);

        __syncthreads();   // previous compute must finish before we overwrite smem

        As[loadCol + 0][loadRow] = a0.x;
        As[loadCol + 1][loadRow] = a0.y;
        As[loadCol + 2][loadRow] = a0.z;
        As[loadCol + 3][loadRow] = a0.w;
        As[loadCol + 0][loadRow + 64] = a1.x;
        As[loadCol + 1][loadRow + 64] = a1.y;
        As[loadCol + 2][loadRow + 64] = a1.z;
        As[loadCol + 3][loadRow + 64] = a1.w;

        Bs[loadCol + 0][loadRow] = b0.x;
        Bs[loadCol + 1][loadRow] = b0.y;
        Bs[loadCol + 2][loadRow] = b0.z;
        Bs[loadCol + 3][loadRow] = b0.w;
        Bs[loadCol + 0][loadRow + 64] = b1.x;
        Bs[loadCol + 1][loadRow + 64] = b1.y;
        Bs[loadCol + 2][loadRow + 64] = b1.z;
        Bs[loadCol + 3][loadRow + 64] = b1.w;

        __syncthreads();

        #pragma unroll
        for (int kk = 0; kk < BK; kk++) {
            float av[8], bv[8];
            #pragma unroll
            for (int ii = 0; ii < 8; ii++) av[ii] = As[kk][ty * 8 + ii];
            #pragma unroll
            for (int jj = 0; jj < 8; jj++) bv[jj] = Bs[kk][tx * 8 + jj];
            #pragma unroll
            for (int ii = 0; ii < 8; ii++)
                #pragma unroll
                for (int jj = 0; jj < 8; jj++)
                    acc[ii][jj] = fmaf(av[ii], bv[jj], acc[ii][jj]);
        }
    }

    // Epilogue
    int i0 = bi * BM + ty * 8;
    int j0 = bj * BN + tx * 8;
    const float inv2M = 1.f / (2.f * MM);

    float di[8], dj[8];
    #pragma unroll
    for (int ii = 0; ii < 8; ii++) di[ii] = g_diag[b * DIM + i0 + ii];
    #pragma unroll
    for (int jj = 0; jj < 8; jj++) dj[jj] = g_diag[b * DIM + j0 + jj];

    float* dc = g_dcov + (size_t)b * DIM * DIM;
    bool mirror = (bi != bj);

    #pragma unroll
    for (int ii = 0; ii < 8; ii++) {
        int i = i0 + ii;
        #pragma unroll
        for (int jj = 0; jj < 8; jj++) {
            int j = j0 + jj;
            float s = acc[ii][jj] * inv2M;
            float d = (i == j) ? 0.f : fmaxf(di[ii] + dj[jj] - 2.f * s, 0.f);
            float v = exp2f(ALPHA * log2f(d + EPS));
            dc[(size_t)i * DIM + j] = v;
            if (mirror) dc[(size_t)j * DIM + i] = v;
        }
    }
}

// ---------------------------------------------------------------------------
// K2: row means. One warp per row of dcov (1024 floats = 8 float4 per lane).
// dcov is symmetric, so row mean == col mean.
// ---------------------------------------------------------------------------
__global__ void rowmean_kernel() {
    int warp = (blockIdx.x * blockDim.x + threadIdx.x) >> 5;
    int lane = threadIdx.x & 31;
    if (warp >= B * DIM) return;
    const float4* row = reinterpret_cast<const float4*>(g_dcov + (size_t)warp * DIM);
    float s = 0.f;
    #pragma unroll
    for (int k = 0; k < 8; k++) {
        float4 v = row[lane + 32 * k];
        s += v.x + v.y + v.z + v.w;
    }
    #pragma unroll
    for (int off = 16; off > 0; off >>= 1)
        s += __shfl_down_sync(0xFFFFFFFFu, s, off);
    if (lane == 0) g_mean[warp] = s * (1.f / DIM);
}

// ---------------------------------------------------------------------------
// K2b: total mean per batch = mean of row means.
// ---------------------------------------------------------------------------
__global__ void totmean_kernel() {
    int b = blockIdx.x;
    __shared__ float sh[256];
    float s = 0.f;
    for (int i = threadIdx.x; i < DIM; i += 256)
        s += g_mean[b * DIM + i];
    sh[threadIdx.x] = s;
    __syncthreads();
    for (int off = 128; off > 0; off >>= 1) {
        if (threadIdx.x < off) sh[threadIdx.x] += sh[threadIdx.x + off];
        __syncthreads();
    }
    if (threadIdx.x == 0) g_tot[b] = sh[0] * (1.f / DIM);
}

// ---------------------------------------------------------------------------
// K3: double-centering + triu extraction.
// One block per (batch, row i); writes out[b][off(i) + (j-i)] for j >= i.
// off(i) = i*DIM - i*(i-1)/2
// ---------------------------------------------------------------------------
__global__ void triu_kernel(float* __restrict__ out) {
    int i = blockIdx.x;
    int b = blockIdx.y;
    int L = DIM - i;
    size_t base = (size_t)b * OUT_PER_B + (size_t)i * DIM - (size_t)(i * (i - 1) / 2);
    const float* row = g_dcov + ((size_t)b * DIM + i) * DIM;
    float mi = g_mean[b * DIM + i];
    float tb = g_tot[b];
    float adj = tb - mi;
    for (int q = threadIdx.x; q < L; q += blockDim.x) {
        int j = i + q;
        out[base + q] = row[j] - g_mean[b * DIM + j] + adj;
    }
}

// ---------------------------------------------------------------------------
extern "C" void kernel_launch(void* const* d_in, const int* in_sizes, int n_in,
                              void* d_out, int out_size) {
    const float* x = (const float*)d_in[0];
    float* out = (float*)d_out;

    diag_kernel<<<(B * DIM) / 8, 256>>>(x);
    gemm_dcov_kernel<<<dim3(NPAIRS, B), 256>>>(x);
    rowmean_kernel<<<(B * DIM) / 8, 256>>>();
    totmean_kernel<<<B, 256>>>();
    triu_kernel<<<dim3(DIM, B), 256>>>(out);
}

// round 3
// speedup vs baseline: 1.9265x; 1.9265x over previous
#include <cuda_runtime.h>
#include <cstdint>

// Problem constants
constexpr int B   = 32;
constexpr int DIM = 1024;
constexpr int MM  = 512;
constexpr int OUT_PER_B = DIM * (DIM + 1) / 2;
constexpr float ALPHA = 0.4f;
constexpr float EPS   = 1e-5f;

// Scratch
__device__ float g_dcov[(size_t)B * DIM * DIM];
__device__ float g_diag[B * DIM];
__device__ float g_mean[B * DIM];
__device__ float g_tot[B];

// ---------------------------------------------------------------------------
// mma.sync tf32 m16n8k8 (portable HMMA path; compute_103-safe)
// ---------------------------------------------------------------------------
__device__ __forceinline__ void mma_tf32(float* c, const uint32_t* a, const uint32_t* b) {
    asm volatile(
        "mma.sync.aligned.m16n8k8.row.col.f32.tf32.tf32.f32 "
        "{%0,%1,%2,%3}, {%4,%5,%6,%7}, {%8,%9}, {%0,%1,%2,%3};"
        : "+f"(c[0]), "+f"(c[1]), "+f"(c[2]), "+f"(c[3])
        : "r"(a[0]), "r"(a[1]), "r"(a[2]), "r"(a[3]), "r"(b[0]), "r"(b[1]));
}
__device__ __forceinline__ uint32_t f2tf32(float f) {
    uint32_t r;
    asm("cvt.rna.tf32.f32 %0, %1;" : "=r"(r) : "f"(f));
    return r;
}

// ---------------------------------------------------------------------------
// K0: diag[b][i] = ||x_i||^2 / (2M)   (exact fp32)
// ---------------------------------------------------------------------------
__global__ void diag_kernel(const float* __restrict__ x) {
    int warp = (blockIdx.x * blockDim.x + threadIdx.x) >> 5;
    int lane = threadIdx.x & 31;
    if (warp >= B * DIM) return;
    const float4* row = reinterpret_cast<const float4*>(x + (size_t)warp * MM);
    float s = 0.f;
    #pragma unroll
    for (int k = 0; k < 4; k++) {
        float4 v = row[lane + 32 * k];
        s += v.x * v.x + v.y * v.y + v.z * v.z + v.w * v.w;
    }
    #pragma unroll
    for (int off = 16; off > 0; off >>= 1)
        s += __shfl_down_sync(0xFFFFFFFFu, s, off);
    if (lane == 0) g_diag[warp] = s * (1.f / (2.f * MM));
}

// ---------------------------------------------------------------------------
// K1: TF32 mma.sync SYRK 128x128 tile + fused dcov epilogue.
// Upper-triangular tiles only, mirrored store.
// ---------------------------------------------------------------------------
constexpr int NTILE  = DIM / 128;               // 8
constexpr int NPAIRS = NTILE * (NTILE + 1) / 2; // 36
constexpr int BK  = 16;
constexpr int SMA = 128 + 4;                    // padded k-major row

__global__ __launch_bounds__(256, 2)
void syrk_dcov_mma(const float* __restrict__ x) {
    __shared__ uint32_t As[BK * SMA];
    __shared__ uint32_t Bs[BK * SMA];

    int tid  = threadIdx.x;
    int wid  = tid >> 5;
    int lane = tid & 31;
    int grp  = lane >> 2;   // 0..7
    int qid  = lane & 3;    // 0..3
    int wm   = wid & 3;     // warp M position (32 rows each)
    int wn   = wid >> 2;    // warp N position (64 cols each)

    // tile decode: blockIdx.x -> (bi, bj), bi <= bj
    int p = blockIdx.x, bi = 0;
    while (p >= NTILE - bi) { p -= NTILE - bi; bi++; }
    int bj = bi + p;
    int b = blockIdx.y;

    const float* Abase = x + ((size_t)b * DIM + bi * 128) * MM;
    const float* Bbase = x + ((size_t)b * DIM + bj * 128) * MM;

    // loader slots: 512 float4 per matrix per k-stage; 2 per thread
    int rowq[2], kcq[2];
    #pragma unroll
    for (int q = 0; q < 2; q++) { int idx = tid + 256 * q; rowq[q] = idx >> 2; kcq[q] = idx & 3; }

    float c[2][8][4] = {};

    float4 pa[2], pb[2];
    #pragma unroll
    for (int q = 0; q < 2; q++) {
        pa[q] = *reinterpret_cast<const float4*>(Abase + (size_t)rowq[q] * MM + kcq[q] * 4);
        pb[q] = *reinterpret_cast<const float4*>(Bbase + (size_t)rowq[q] * MM + kcq[q] * 4);
    }

    for (int k0 = 0; k0 < MM; k0 += BK) {
        __syncthreads();   // previous compute done before overwriting smem
        #pragma unroll
        for (int q = 0; q < 2; q++) {
            int base = kcq[q] * 4 * SMA + rowq[q];
            As[base + 0 * SMA] = f2tf32(pa[q].x);
            As[base + 1 * SMA] = f2tf32(pa[q].y);
            As[base + 2 * SMA] = f2tf32(pa[q].z);
            As[base + 3 * SMA] = f2tf32(pa[q].w);
            Bs[base + 0 * SMA] = f2tf32(pb[q].x);
            Bs[base + 1 * SMA] = f2tf32(pb[q].y);
            Bs[base + 2 * SMA] = f2tf32(pb[q].z);
            Bs[base + 3 * SMA] = f2tf32(pb[q].w);
        }
        __syncthreads();

        // prefetch next stage
        if (k0 + BK < MM) {
            #pragma unroll
            for (int q = 0; q < 2; q++) {
                pa[q] = *reinterpret_cast<const float4*>(Abase + (size_t)rowq[q] * MM + k0 + BK + kcq[q] * 4);
                pb[q] = *reinterpret_cast<const float4*>(Bbase + (size_t)rowq[q] * MM + k0 + BK + kcq[q] * 4);
            }
        }

        #pragma unroll
        for (int ks = 0; ks < 2; ks++) {
            int k = ks * 8;
            uint32_t af[2][4];
            #pragma unroll
            for (int mt = 0; mt < 2; mt++) {
                int m = wm * 32 + mt * 16 + grp;
                af[mt][0] = As[(k + qid) * SMA + m];
                af[mt][1] = As[(k + qid) * SMA + m + 8];
                af[mt][2] = As[(k + 4 + qid) * SMA + m];
                af[mt][3] = As[(k + 4 + qid) * SMA + m + 8];
            }
            uint32_t bf[8][2];
            #pragma unroll
            for (int nt = 0; nt < 8; nt++) {
                int n = wn * 64 + nt * 8 + grp;
                bf[nt][0] = Bs[(k + qid) * SMA + n];
                bf[nt][1] = Bs[(k + 4 + qid) * SMA + n];
            }
            #pragma unroll
            for (int mt = 0; mt < 2; mt++)
                #pragma unroll
                for (int nt = 0; nt < 8; nt++)
                    mma_tf32(c[mt][nt], af[mt], bf[nt]);
        }
    }

    // Epilogue: dcov transform + store (row-major + mirror)
    int i0 = bi * 128, j0 = bj * 128;
    const float invM = 1.f / (float)MM;
    float* dcb = g_dcov + (size_t)b * DIM * DIM;
    bool mirror = (bi != bj);
    const float* dgb = g_diag + b * DIM;

    float dj[8][2];
    #pragma unroll
    for (int nt = 0; nt < 8; nt++) {
        int j = j0 + wn * 64 + nt * 8 + 2 * qid;
        dj[nt][0] = dgb[j];
        dj[nt][1] = dgb[j + 1];
    }

    #pragma unroll
    for (int mt = 0; mt < 2; mt++) {
        #pragma unroll
        for (int rr = 0; rr < 2; rr++) {
            int i = i0 + wm * 32 + mt * 16 + grp + rr * 8;
            float di = dgb[i - i0 + i0];  // = dgb[i]
            #pragma unroll
            for (int nt = 0; nt < 8; nt++) {
                int j = j0 + wn * 64 + nt * 8 + 2 * qid;
                float dot0 = c[mt][nt][rr * 2 + 0];
                float dot1 = c[mt][nt][rr * 2 + 1];
                float d0 = (i == j)     ? 0.f : fmaxf(di + dj[nt][0] - dot0 * invM, 0.f);
                float d1 = (i == j + 1) ? 0.f : fmaxf(di + dj[nt][1] - dot1 * invM, 0.f);
                float v0 = exp2f(ALPHA * log2f(d0 + EPS));
                float v1 = exp2f(ALPHA * log2f(d1 + EPS));
                *reinterpret_cast<float2*>(dcb + (size_t)i * DIM + j) = make_float2(v0, v1);
                if (mirror) {
                    dcb[(size_t)j * DIM + i]       = v0;
                    dcb[(size_t)(j + 1) * DIM + i] = v1;
                }
            }
        }
    }
}

// ---------------------------------------------------------------------------
// K2: row means (symmetric -> also col means)
// ---------------------------------------------------------------------------
__global__ void rowmean_kernel() {
    int warp = (blockIdx.x * blockDim.x + threadIdx.x) >> 5;
    int lane = threadIdx.x & 31;
    if (warp >= B * DIM) return;
    const float4* row = reinterpret_cast<const float4*>(g_dcov + (size_t)warp * DIM);
    float s = 0.f;
    #pragma unroll
    for (int k = 0; k < 8; k++) {
        float4 v = row[lane + 32 * k];
        s += v.x + v.y + v.z + v.w;
    }
    #pragma unroll
    for (int off = 16; off > 0; off >>= 1)
        s += __shfl_down_sync(0xFFFFFFFFu, s, off);
    if (lane == 0) g_mean[warp] = s * (1.f / DIM);
}

__global__ void totmean_kernel() {
    int b = blockIdx.x;
    __shared__ float sh[256];
    float s = 0.f;
    for (int i = threadIdx.x; i < DIM; i += 256)
        s += g_mean[b * DIM + i];
    sh[threadIdx.x] = s;
    __syncthreads();
    for (int off = 128; off > 0; off >>= 1) {
        if (threadIdx.x < off) sh[threadIdx.x] += sh[threadIdx.x + off];
        __syncthreads();
    }
    if (threadIdx.x == 0) g_tot[b] = sh[0] * (1.f / DIM);
}

// ---------------------------------------------------------------------------
// K3: double-centering + triu extraction
// ---------------------------------------------------------------------------
__global__ void triu_kernel(float* __restrict__ out) {
    int i = blockIdx.x;
    int b = blockIdx.y;
    int L = DIM - i;
    size_t base = (size_t)b * OUT_PER_B + (size_t)i * DIM - (size_t)(i * (i - 1) / 2);
    const float* row = g_dcov + ((size_t)b * DIM + i) * DIM;
    float adj = g_tot[b] - g_mean[b * DIM + i];
    for (int q = threadIdx.x; q < L; q += blockDim.x) {
        int j = i + q;
        out[base + q] = row[j] - g_mean[b * DIM + j] + adj;
    }
}

// ---------------------------------------------------------------------------
extern "C" void kernel_launch(void* const* d_in, const int* in_sizes, int n_in,
                              void* d_out, int out_size) {
    const float* x = (const float*)d_in[0];
    float* out = (float*)d_out;

    diag_kernel<<<(B * DIM) / 8, 256>>>(x);
    syrk_dcov_mma<<<dim3(NPAIRS, B), 256>>>(x);
    rowmean_kernel<<<(B * DIM) / 8, 256>>>();
    totmean_kernel<<<B, 256>>>();
    triu_kernel<<<dim3(DIM, B), 256>>>(out);
}

// round 4
// speedup vs baseline: 2.1973x; 1.1406x over previous
#include <cuda_runtime.h>
#include <cstdint>

// Problem constants
constexpr int B   = 32;
constexpr int DIM = 1024;
constexpr int MM  = 512;
constexpr int OUT_PER_B = DIM * (DIM + 1) / 2;
constexpr float ALPHA = 0.4f;
constexpr float EPS   = 1e-5f;

// Scratch
__device__ float g_dcov[(size_t)B * DIM * DIM];   // upper tiles only
__device__ float g_diag[B * DIM];
__device__ float g_part[B * 8 * 8 * 128];         // per-tile row-sum contributions
__device__ float g_mean[B * DIM];
__device__ float g_tot[B];

// ---------------------------------------------------------------------------
// mma.sync tf32 m16n8k8 (portable HMMA path; compute_103-safe)
// ---------------------------------------------------------------------------
__device__ __forceinline__ void mma_tf32(float* c, const uint32_t* a, const uint32_t* b) {
    asm volatile(
        "mma.sync.aligned.m16n8k8.row.col.f32.tf32.tf32.f32 "
        "{%0,%1,%2,%3}, {%4,%5,%6,%7}, {%8,%9}, {%0,%1,%2,%3};"
        : "+f"(c[0]), "+f"(c[1]), "+f"(c[2]), "+f"(c[3])
        : "r"(a[0]), "r"(a[1]), "r"(a[2]), "r"(a[3]), "r"(b[0]), "r"(b[1]));
}
__device__ __forceinline__ uint32_t f2tf32(float f) {
    uint32_t r;
    asm("cvt.rna.tf32.f32 %0, %1;" : "=r"(r) : "f"(f));
    return r;
}

// ---------------------------------------------------------------------------
// K0: diag[b][i] = ||x_i||^2 / (2M)   (exact fp32)
// ---------------------------------------------------------------------------
__global__ void diag_kernel(const float* __restrict__ x) {
    int warp = (blockIdx.x * blockDim.x + threadIdx.x) >> 5;
    int lane = threadIdx.x & 31;
    if (warp >= B * DIM) return;
    const float4* row = reinterpret_cast<const float4*>(x + (size_t)warp * MM);
    float s = 0.f;
    #pragma unroll
    for (int k = 0; k < 4; k++) {
        float4 v = row[lane + 32 * k];
        s += v.x * v.x + v.y * v.y + v.z * v.z + v.w * v.w;
    }
    #pragma unroll
    for (int off = 16; off > 0; off >>= 1)
        s += __shfl_down_sync(0xFFFFFFFFu, s, off);
    if (lane == 0) g_diag[warp] = s * (1.f / (2.f * MM));
}

// ---------------------------------------------------------------------------
// K1: TF32 mma.sync SYRK 128x128 tile + fused dcov epilogue.
// Upper-triangular tiles only; NO mirror store. Row/col sums of each tile are
// reduced deterministically and written to g_part (col sums feed the mirrored
// tile's row sums by symmetry).
// ---------------------------------------------------------------------------
constexpr int NTILE  = DIM / 128;               // 8
constexpr int NPAIRS = NTILE * (NTILE + 1) / 2; // 36
constexpr int BK  = 16;
constexpr int SMA = 128 + 4;                    // padded k-major row

__global__ __launch_bounds__(256, 2)
void syrk_dcov_mma(const float* __restrict__ x) {
    __shared__ uint32_t As[BK * SMA];
    __shared__ uint32_t Bs[BK * SMA];

    int tid  = threadIdx.x;
    int wid  = tid >> 5;
    int lane = tid & 31;
    int grp  = lane >> 2;   // 0..7
    int qid  = lane & 3;    // 0..3
    int wm   = wid & 3;     // warp M position (32 rows each)
    int wn   = wid >> 2;    // warp N position (64 cols each)

    // tile decode: blockIdx.x -> (bi, bj), bi <= bj
    int p = blockIdx.x, bi = 0;
    while (p >= NTILE - bi) { p -= NTILE - bi; bi++; }
    int bj = bi + p;
    int b = blockIdx.y;

    const float* Abase = x + ((size_t)b * DIM + bi * 128) * MM;
    const float* Bbase = x + ((size_t)b * DIM + bj * 128) * MM;

    int rowq[2], kcq[2];
    #pragma unroll
    for (int q = 0; q < 2; q++) { int idx = tid + 256 * q; rowq[q] = idx >> 2; kcq[q] = idx & 3; }

    float c[2][8][4] = {};

    float4 pa[2], pb[2];
    #pragma unroll
    for (int q = 0; q < 2; q++) {
        pa[q] = *reinterpret_cast<const float4*>(Abase + (size_t)rowq[q] * MM + kcq[q] * 4);
        pb[q] = *reinterpret_cast<const float4*>(Bbase + (size_t)rowq[q] * MM + kcq[q] * 4);
    }

    for (int k0 = 0; k0 < MM; k0 += BK) {
        __syncthreads();
        #pragma unroll
        for (int q = 0; q < 2; q++) {
            int base = kcq[q] * 4 * SMA + rowq[q];
            As[base + 0 * SMA] = f2tf32(pa[q].x);
            As[base + 1 * SMA] = f2tf32(pa[q].y);
            As[base + 2 * SMA] = f2tf32(pa[q].z);
            As[base + 3 * SMA] = f2tf32(pa[q].w);
            Bs[base + 0 * SMA] = f2tf32(pb[q].x);
            Bs[base + 1 * SMA] = f2tf32(pb[q].y);
            Bs[base + 2 * SMA] = f2tf32(pb[q].z);
            Bs[base + 3 * SMA] = f2tf32(pb[q].w);
        }
        __syncthreads();

        if (k0 + BK < MM) {
            #pragma unroll
            for (int q = 0; q < 2; q++) {
                pa[q] = *reinterpret_cast<const float4*>(Abase + (size_t)rowq[q] * MM + k0 + BK + kcq[q] * 4);
                pb[q] = *reinterpret_cast<const float4*>(Bbase + (size_t)rowq[q] * MM + k0 + BK + kcq[q] * 4);
            }
        }

        #pragma unroll
        for (int ks = 0; ks < 2; ks++) {
            int k = ks * 8;
            uint32_t af[2][4];
            #pragma unroll
            for (int mt = 0; mt < 2; mt++) {
                int m = wm * 32 + mt * 16 + grp;
                af[mt][0] = As[(k + qid) * SMA + m];
                af[mt][1] = As[(k + qid) * SMA + m + 8];
                af[mt][2] = As[(k + 4 + qid) * SMA + m];
                af[mt][3] = As[(k + 4 + qid) * SMA + m + 8];
            }
            uint32_t bf[8][2];
            #pragma unroll
            for (int nt = 0; nt < 8; nt++) {
                int n = wn * 64 + nt * 8 + grp;
                bf[nt][0] = Bs[(k + qid) * SMA + n];
                bf[nt][1] = Bs[(k + 4 + qid) * SMA + n];
            }
            #pragma unroll
            for (int mt = 0; mt < 2; mt++)
                #pragma unroll
                for (int nt = 0; nt < 8; nt++)
                    mma_tf32(c[mt][nt], af[mt], bf[nt]);
        }
    }

    // ---------------- Epilogue ----------------
    int i0 = bi * 128, j0 = bj * 128;
    const float invM = 1.f / (float)MM;
    float* dcb = g_dcov + (size_t)b * DIM * DIM;
    bool offdiag = (bi != bj);
    const float* dgb = g_diag + b * DIM;

    float dj[8][2];
    #pragma unroll
    for (int nt = 0; nt < 8; nt++) {
        int j = j0 + wn * 64 + nt * 8 + 2 * qid;
        dj[nt][0] = dgb[j];
        dj[nt][1] = dgb[j + 1];
    }

    float rsum[2][2] = {};
    float csum[8][2] = {};

    #pragma unroll
    for (int mt = 0; mt < 2; mt++) {
        #pragma unroll
        for (int rr = 0; rr < 2; rr++) {
            int i = i0 + wm * 32 + mt * 16 + grp + rr * 8;
            float di = dgb[i - i0 + i0];
            #pragma unroll
            for (int nt = 0; nt < 8; nt++) {
                int j = j0 + wn * 64 + nt * 8 + 2 * qid;
                float dot0 = c[mt][nt][rr * 2 + 0];
                float dot1 = c[mt][nt][rr * 2 + 1];
                float d0 = (i == j)     ? 0.f : fmaxf(di + dj[nt][0] - dot0 * invM, 0.f);
                float d1 = (i == j + 1) ? 0.f : fmaxf(di + dj[nt][1] - dot1 * invM, 0.f);
                float v0 = exp2f(ALPHA * log2f(d0 + EPS));
                float v1 = exp2f(ALPHA * log2f(d1 + EPS));
                *reinterpret_cast<float2*>(dcb + (size_t)i * DIM + j) = make_float2(v0, v1);
                rsum[mt][rr] += v0 + v1;
                csum[nt][0]  += v0;
                csum[nt][1]  += v1;
            }
        }
    }

    // intra-warp reductions:
    // rows: reduce over qid (lanes xor 1,2)
    #pragma unroll
    for (int mt = 0; mt < 2; mt++)
        #pragma unroll
        for (int rr = 0; rr < 2; rr++) {
            rsum[mt][rr] += __shfl_xor_sync(0xFFFFFFFFu, rsum[mt][rr], 1);
            rsum[mt][rr] += __shfl_xor_sync(0xFFFFFFFFu, rsum[mt][rr], 2);
        }
    // cols: reduce over grp (lanes xor 4,8,16)
    #pragma unroll
    for (int nt = 0; nt < 8; nt++)
        #pragma unroll
        for (int h = 0; h < 2; h++) {
            csum[nt][h] += __shfl_xor_sync(0xFFFFFFFFu, csum[nt][h], 4);
            csum[nt][h] += __shfl_xor_sync(0xFFFFFFFFu, csum[nt][h], 8);
            csum[nt][h] += __shfl_xor_sync(0xFFFFFFFFu, csum[nt][h], 16);
        }

    // cross-warp via smem (reuse As): rbuf[2][128], cbuf[4][128]
    __syncthreads();
    float* rbuf = reinterpret_cast<float*>(As);        // 256 floats
    float* cbuf = rbuf + 256;                          // 512 floats
    if (qid == 0) {
        #pragma unroll
        for (int mt = 0; mt < 2; mt++)
            #pragma unroll
            for (int rr = 0; rr < 2; rr++)
                rbuf[wn * 128 + wm * 32 + mt * 16 + rr * 8 + grp] = rsum[mt][rr];
    }
    if (grp == 0) {
        #pragma unroll
        for (int nt = 0; nt < 8; nt++) {
            cbuf[wm * 128 + wn * 64 + nt * 8 + 2 * qid + 0] = csum[nt][0];
            cbuf[wm * 128 + wn * 64 + nt * 8 + 2 * qid + 1] = csum[nt][1];
        }
    }
    __syncthreads();

    if (tid < 128) {
        float rs = rbuf[tid] + rbuf[128 + tid];
        g_part[(((size_t)b * 8 + bi) * 8 + bj) * 128 + tid] = rs;
    } else if (offdiag) {
        int t = tid - 128;
        float cs = cbuf[t] + cbuf[128 + t] + cbuf[256 + t] + cbuf[384 + t];
        g_part[(((size_t)b * 8 + bj) * 8 + bi) * 128 + t] = cs;
    }
}

// ---------------------------------------------------------------------------
// K2: assemble row means from per-tile partials (1MB read; deterministic)
// ---------------------------------------------------------------------------
__global__ void meanreduce_kernel() {
    int idx = blockIdx.x * 256 + threadIdx.x;     // 0 .. 32767
    int b  = idx >> 10;
    int i  = idx & 1023;
    int ti = i >> 7;
    int ii = i & 127;
    float s = 0.f;
    #pragma unroll
    for (int tj = 0; tj < 8; tj++)
        s += g_part[(((size_t)b * 8 + ti) * 8 + tj) * 128 + ii];
    g_mean[idx] = s * (1.f / DIM);
}

__global__ void totmean_kernel() {
    int b = blockIdx.x;
    __shared__ float sh[256];
    float s = 0.f;
    for (int i = threadIdx.x; i < DIM; i += 256)
        s += g_mean[b * DIM + i];
    sh[threadIdx.x] = s;
    __syncthreads();
    for (int off = 128; off > 0; off >>= 1) {
        if (threadIdx.x < off) sh[threadIdx.x] += sh[threadIdx.x + off];
        __syncthreads();
    }
    if (threadIdx.x == 0) g_tot[b] = sh[0] * (1.f / DIM);
}

// ---------------------------------------------------------------------------
// K3: double-centering + triu extraction (reads upper triangle only)
// ---------------------------------------------------------------------------
__global__ void triu_kernel(float* __restrict__ out) {
    int i = blockIdx.x;
    int b = blockIdx.y;
    int L = DIM - i;
    size_t base = (size_t)b * OUT_PER_B + (size_t)i * DIM - (size_t)(i * (i - 1) / 2);
    const float* row = g_dcov + ((size_t)b * DIM + i) * DIM;
    float adj = g_tot[b] - g_mean[b * DIM + i];
    for (int q = threadIdx.x; q < L; q += blockDim.x) {
        int j = i + q;
        out[base + q] = row[j] - g_mean[b * DIM + j] + adj;
    }
}

// ---------------------------------------------------------------------------
extern "C" void kernel_launch(void* const* d_in, const int* in_sizes, int n_in,
                              void* d_out, int out_size) {
    const float* x = (const float*)d_in[0];
    float* out = (float*)d_out;

    diag_kernel<<<(B * DIM) / 8, 256>>>(x);
    syrk_dcov_mma<<<dim3(NPAIRS, B), 256>>>(x);
    meanreduce_kernel<<<(B * DIM) / 256, 256>>>();
    totmean_kernel<<<B, 256>>>();
    triu_kernel<<<dim3(DIM, B), 256>>>(out);
}

// round 5
// speedup vs baseline: 2.9122x; 1.3254x over previous
#include <cuda_runtime.h>
#include <cstdint>

// Problem constants
constexpr int B   = 32;
constexpr int DIM = 1024;
constexpr int MM  = 512;
constexpr int OUT_PER_B = DIM * (DIM + 1) / 2;
constexpr float ALPHA = 0.4f;
constexpr float EPS   = 1e-5f;

// Scratch
__device__ float g_dcov[(size_t)B * DIM * DIM];   // upper tiles only
__device__ float g_diag[B * DIM];
__device__ float g_part[B * 8 * 8 * 128];
__device__ float g_mean[B * DIM];
__device__ float g_tot[B];

// ---------------------------------------------------------------------------
__device__ __forceinline__ void mma_tf32(float* c, const uint32_t* a, const uint32_t* b) {
    asm volatile(
        "mma.sync.aligned.m16n8k8.row.col.f32.tf32.tf32.f32 "
        "{%0,%1,%2,%3}, {%4,%5,%6,%7}, {%8,%9}, {%0,%1,%2,%3};"
        : "+f"(c[0]), "+f"(c[1]), "+f"(c[2]), "+f"(c[3])
        : "r"(a[0]), "r"(a[1]), "r"(a[2]), "r"(a[3]), "r"(b[0]), "r"(b[1]));
}
__device__ __forceinline__ uint32_t smem_u32(const void* p) {
    uint32_t a;
    asm("{ .reg .u64 t; cvta.to.shared.u64 t, %1; cvt.u32.u64 %0, t; }" : "=r"(a) : "l"(p));
    return a;
}
__device__ __forceinline__ void cp16(uint32_t saddr, const void* g) {
    asm volatile("cp.async.cg.shared.global [%0], [%1], 16;" :: "r"(saddr), "l"(g));
}
#define CP_COMMIT() asm volatile("cp.async.commit_group;" ::: "memory")
#define CP_WAIT1()  asm volatile("cp.async.wait_group 1;" ::: "memory")

// ---------------------------------------------------------------------------
// K0: diag[b][i] = ||x_i||^2 / (2M)   (exact fp32)
// ---------------------------------------------------------------------------
__global__ void diag_kernel(const float* __restrict__ x) {
    int warp = (blockIdx.x * blockDim.x + threadIdx.x) >> 5;
    int lane = threadIdx.x & 31;
    if (warp >= B * DIM) return;
    const float4* row = reinterpret_cast<const float4*>(x + (size_t)warp * MM);
    float s = 0.f;
    #pragma unroll
    for (int k = 0; k < 4; k++) {
        float4 v = row[lane + 32 * k];
        s += v.x * v.x + v.y * v.y + v.z * v.z + v.w * v.w;
    }
    #pragma unroll
    for (int off = 16; off > 0; off >>= 1)
        s += __shfl_down_sync(0xFFFFFFFFu, s, off);
    if (lane == 0) g_diag[warp] = s * (1.f / (2.f * MM));
}

// ---------------------------------------------------------------------------
// K1: TF32 mma.sync SYRK 128x128 tile, cp.async 3-stage pipeline,
//     fused dcov epilogue + deterministic row/col partial sums.
// ---------------------------------------------------------------------------
constexpr int NTILE  = DIM / 128;
constexpr int NPAIRS = NTILE * (NTILE + 1) / 2;   // 36
constexpr int BK     = 32;
constexpr int NITER  = MM / BK;                   // 16
constexpr int STAGES = 3;
constexpr int ROWP   = BK + 4;                    // 36 floats row stride
constexpr int STAGE_FLOATS = 128 * ROWP;          // 4608
constexpr int SMEM_BYTES = STAGES * 2 * STAGE_FLOATS * 4;  // 110592

__global__ __launch_bounds__(256, 2)
void syrk_dcov_mma(const float* __restrict__ x) {
    extern __shared__ float smem[];
    uint32_t sbase = smem_u32(smem);

    int tid  = threadIdx.x;
    int wid  = tid >> 5;
    int lane = tid & 31;
    int grp  = lane >> 2;
    int qid  = lane & 3;
    int wm   = wid & 3;     // warp M (32 rows)
    int wn   = wid >> 2;    // warp N (64 cols)

    int p = blockIdx.x, bi = 0;
    while (p >= NTILE - bi) { p -= NTILE - bi; bi++; }
    int bj = bi + p;
    int b = blockIdx.y;

    const float* Abase = x + ((size_t)b * DIM + bi * 128) * MM;
    const float* Bbase = x + ((size_t)b * DIM + bj * 128) * MM;

    // cp.async slots: 4 chunks of 16B per matrix per thread per stage
    const float* gA[4];
    const float* gB[4];
    uint32_t soff[4];
    #pragma unroll
    for (int q = 0; q < 4; q++) {
        int idx = tid + 256 * q;
        int row = idx >> 3;
        int c   = idx & 7;
        gA[q] = Abase + (size_t)row * MM + c * 4;
        gB[q] = Bbase + (size_t)row * MM + c * 4;
        soff[q] = (uint32_t)(row * ROWP + c * 4) * 4u;
    }

    auto issue = [&](int s) {
        int buf = s % STAGES;
        int k0  = s * BK;
        uint32_t ab = sbase + (uint32_t)buf * (2 * STAGE_FLOATS * 4);
        uint32_t bb = ab + STAGE_FLOATS * 4;
        #pragma unroll
        for (int q = 0; q < 4; q++) {
            cp16(ab + soff[q], gA[q] + k0);
            cp16(bb + soff[q], gB[q] + k0);
        }
    };

    float c[2][8][4] = {};

    issue(0); CP_COMMIT();
    issue(1); CP_COMMIT();

    for (int it = 0; it < NITER; it++) {
        CP_WAIT1();
        __syncthreads();

        if (it + 2 < NITER) issue(it + 2);
        CP_COMMIT();

        const float* A0 = smem + (it % STAGES) * (2 * STAGE_FLOATS);
        const float* B0 = A0 + STAGE_FLOATS;

        #pragma unroll
        for (int ks = 0; ks < 4; ks++) {
            int kk = ks * 8;
            uint32_t af[2][4];
            #pragma unroll
            for (int mt = 0; mt < 2; mt++) {
                int m = wm * 32 + mt * 16 + grp;
                af[mt][0] = __float_as_uint(A0[m * ROWP + kk + qid]);
                af[mt][1] = __float_as_uint(A0[(m + 8) * ROWP + kk + qid]);
                af[mt][2] = __float_as_uint(A0[m * ROWP + kk + 4 + qid]);
                af[mt][3] = __float_as_uint(A0[(m + 8) * ROWP + kk + 4 + qid]);
            }
            uint32_t bf[8][2];
            #pragma unroll
            for (int nt = 0; nt < 8; nt++) {
                int n = wn * 64 + nt * 8 + grp;
                bf[nt][0] = __float_as_uint(B0[n * ROWP + kk + qid]);
                bf[nt][1] = __float_as_uint(B0[n * ROWP + kk + 4 + qid]);
            }
            #pragma unroll
            for (int mt = 0; mt < 2; mt++)
                #pragma unroll
                for (int nt = 0; nt < 8; nt++)
                    mma_tf32(c[mt][nt], af[mt], bf[nt]);
        }
    }

    // ---------------- Epilogue ----------------
    int i0 = bi * 128, j0 = bj * 128;
    const float invM = 1.f / (float)MM;
    float* dcb = g_dcov + (size_t)b * DIM * DIM;
    bool offdiag = (bi != bj);
    const float* dgb = g_diag + b * DIM;

    float dj[8][2];
    #pragma unroll
    for (int nt = 0; nt < 8; nt++) {
        int j = j0 + wn * 64 + nt * 8 + 2 * qid;
        dj[nt][0] = dgb[j];
        dj[nt][1] = dgb[j + 1];
    }

    float rsum[2][2] = {};
    float csum[8][2] = {};

    #pragma unroll
    for (int mt = 0; mt < 2; mt++) {
        #pragma unroll
        for (int rr = 0; rr < 2; rr++) {
            int i = i0 + wm * 32 + mt * 16 + grp + rr * 8;
            float di = dgb[i - i0 + i0];
            #pragma unroll
            for (int nt = 0; nt < 8; nt++) {
                int j = j0 + wn * 64 + nt * 8 + 2 * qid;
                float dot0 = c[mt][nt][rr * 2 + 0];
                float dot1 = c[mt][nt][rr * 2 + 1];
                float d0 = (i == j)     ? 0.f : fmaxf(di + dj[nt][0] - dot0 * invM, 0.f);
                float d1 = (i == j + 1) ? 0.f : fmaxf(di + dj[nt][1] - dot1 * invM, 0.f);
                float v0 = exp2f(ALPHA * log2f(d0 + EPS));
                float v1 = exp2f(ALPHA * log2f(d1 + EPS));
                *reinterpret_cast<float2*>(dcb + (size_t)i * DIM + j) = make_float2(v0, v1);
                rsum[mt][rr] += v0 + v1;
                csum[nt][0]  += v0;
                csum[nt][1]  += v1;
            }
        }
    }

    #pragma unroll
    for (int mt = 0; mt < 2; mt++)
        #pragma unroll
        for (int rr = 0; rr < 2; rr++) {
            rsum[mt][rr] += __shfl_xor_sync(0xFFFFFFFFu, rsum[mt][rr], 1);
            rsum[mt][rr] += __shfl_xor_sync(0xFFFFFFFFu, rsum[mt][rr], 2);
        }
    #pragma unroll
    for (int nt = 0; nt < 8; nt++)
        #pragma unroll
        for (int h = 0; h < 2; h++) {
            csum[nt][h] += __shfl_xor_sync(0xFFFFFFFFu, csum[nt][h], 4);
            csum[nt][h] += __shfl_xor_sync(0xFFFFFFFFu, csum[nt][h], 8);
            csum[nt][h] += __shfl_xor_sync(0xFFFFFFFFu, csum[nt][h], 16);
        }

    __syncthreads();
    float* rbuf = smem;          // 256 floats
    float* cbuf = smem + 256;    // 512 floats
    if (qid == 0) {
        #pragma unroll
        for (int mt = 0; mt < 2; mt++)
            #pragma unroll
            for (int rr = 0; rr < 2; rr++)
                rbuf[wn * 128 + wm * 32 + mt * 16 + rr * 8 + grp] = rsum[mt][rr];
    }
    if (grp == 0) {
        #pragma unroll
        for (int nt = 0; nt < 8; nt++) {
            cbuf[wm * 128 + wn * 64 + nt * 8 + 2 * qid + 0] = csum[nt][0];
            cbuf[wm * 128 + wn * 64 + nt * 8 + 2 * qid + 1] = csum[nt][1];
        }
    }
    __syncthreads();

    if (tid < 128) {
        float rs = rbuf[tid] + rbuf[128 + tid];
        g_part[(((size_t)b * 8 + bi) * 8 + bj) * 128 + tid] = rs;
    } else if (offdiag) {
        int t = tid - 128;
        float cs = cbuf[t] + cbuf[128 + t] + cbuf[256 + t] + cbuf[384 + t];
        g_part[(((size_t)b * 8 + bj) * 8 + bi) * 128 + t] = cs;
    }
}

// ---------------------------------------------------------------------------
// K2: assemble row means from per-tile partials
// ---------------------------------------------------------------------------
__global__ void meanreduce_kernel() {
    int idx = blockIdx.x * 256 + threadIdx.x;
    int b  = idx >> 10;
    int i  = idx & 1023;
    int ti = i >> 7;
    int ii = i & 127;
    float s = 0.f;
    #pragma unroll
    for (int tj = 0; tj < 8; tj++)
        s += g_part[(((size_t)b * 8 + ti) * 8 + tj) * 128 + ii];
    g_mean[idx] = s * (1.f / DIM);
}

__global__ void totmean_kernel() {
    int b = blockIdx.x;
    __shared__ float sh[256];
    float s = 0.f;
    for (int i = threadIdx.x; i < DIM; i += 256)
        s += g_mean[b * DIM + i];
    sh[threadIdx.x] = s;
    __syncthreads();
    for (int off = 128; off > 0; off >>= 1) {
        if (threadIdx.x < off) sh[threadIdx.x] += sh[threadIdx.x + off];
        __syncthreads();
    }
    if (threadIdx.x == 0) g_tot[b] = sh[0] * (1.f / DIM);
}

// ---------------------------------------------------------------------------
// K3: double-centering + triu extraction
// ---------------------------------------------------------------------------
__global__ void triu_kernel(float* __restrict__ out) {
    int i = blockIdx.x;
    int b = blockIdx.y;
    int L = DIM - i;
    size_t base = (size_t)b * OUT_PER_B + (size_t)i * DIM - (size_t)(i * (i - 1) / 2);
    const float* row = g_dcov + ((size_t)b * DIM + i) * DIM;
    float adj = g_tot[b] - g_mean[b * DIM + i];
    for (int q = threadIdx.x; q < L; q += blockDim.x) {
        int j = i + q;
        out[base + q] = row[j] - g_mean[b * DIM + j] + adj;
    }
}

// ---------------------------------------------------------------------------
extern "C" void kernel_launch(void* const* d_in, const int* in_sizes, int n_in,
                              void* d_out, int out_size) {
    const float* x = (const float*)d_in[0];
    float* out = (float*)d_out;

    static bool attr_set = false;
    if (!attr_set) {
        cudaFuncSetAttribute(syrk_dcov_mma,
                             cudaFuncAttributeMaxDynamicSharedMemorySize, SMEM_BYTES);
        attr_set = true;
    }

    diag_kernel<<<(B * DIM) / 8, 256>>>(x);
    syrk_dcov_mma<<<dim3(NPAIRS, B), 256, SMEM_BYTES>>>(x);
    meanreduce_kernel<<<(B * DIM) / 256, 256>>>();
    totmean_kernel<<<B, 256>>>();
    triu_kernel<<<dim3(DIM, B), 256>>>(out);
}

// round 6
// speedup vs baseline: 3.1118x; 1.0685x over previous
#include <cuda_runtime.h>
#include <cstdint>

// Problem constants
constexpr int B   = 32;
constexpr int DIM = 1024;
constexpr int MM  = 512;
constexpr int OUT_PER_B = DIM * (DIM + 1) / 2;
constexpr float ALPHA = 0.4f;
constexpr float EPS   = 1e-5f;

// Scratch
__device__ float g_dcov[(size_t)B * DIM * DIM];   // upper tiles only
__device__ float g_diag[B * DIM];
__device__ float g_part[B * 8 * 8 * 128];
__device__ float g_mean[B * DIM];
__device__ float g_tot[B];

// ---------------------------------------------------------------------------
__device__ __forceinline__ void mma_tf32(float* c, const uint32_t* a, const uint32_t* b) {
    asm volatile(
        "mma.sync.aligned.m16n8k8.row.col.f32.tf32.tf32.f32 "
        "{%0,%1,%2,%3}, {%4,%5,%6,%7}, {%8,%9}, {%0,%1,%2,%3};"
        : "+f"(c[0]), "+f"(c[1]), "+f"(c[2]), "+f"(c[3])
        : "r"(a[0]), "r"(a[1]), "r"(a[2]), "r"(a[3]), "r"(b[0]), "r"(b[1]));
}
__device__ __forceinline__ void ldsm_x4(uint32_t& r0, uint32_t& r1, uint32_t& r2,
                                        uint32_t& r3, uint32_t addr) {
    asm volatile("ldmatrix.sync.aligned.m8n8.x4.shared.b16 {%0,%1,%2,%3}, [%4];"
        : "=r"(r0), "=r"(r1), "=r"(r2), "=r"(r3) : "r"(addr));
}
__device__ __forceinline__ uint32_t smem_u32(const void* p) {
    uint32_t a;
    asm("{ .reg .u64 t; cvta.to.shared.u64 t, %1; cvt.u32.u64 %0, t; }" : "=r"(a) : "l"(p));
    return a;
}
__device__ __forceinline__ void cp16(uint32_t saddr, const void* g) {
    asm volatile("cp.async.cg.shared.global [%0], [%1], 16;" :: "r"(saddr), "l"(g));
}
#define CP_COMMIT() asm volatile("cp.async.commit_group;" ::: "memory")
#define CP_WAIT1()  asm volatile("cp.async.wait_group 1;" ::: "memory")

// ---------------------------------------------------------------------------
// K0: diag[b][i] = ||x_i||^2 / (2M)   (exact fp32)
// ---------------------------------------------------------------------------
__global__ void diag_kernel(const float* __restrict__ x) {
    int warp = (blockIdx.x * blockDim.x + threadIdx.x) >> 5;
    int lane = threadIdx.x & 31;
    if (warp >= B * DIM) return;
    const float4* row = reinterpret_cast<const float4*>(x + (size_t)warp * MM);
    float s = 0.f;
    #pragma unroll
    for (int k = 0; k < 4; k++) {
        float4 v = row[lane + 32 * k];
        s += v.x * v.x + v.y * v.y + v.z * v.z + v.w * v.w;
    }
    #pragma unroll
    for (int off = 16; off > 0; off >>= 1)
        s += __shfl_down_sync(0xFFFFFFFFu, s, off);
    if (lane == 0) g_diag[warp] = s * (1.f / (2.f * MM));
}

// ---------------------------------------------------------------------------
// K1: TF32 mma.sync SYRK 128x128 tile, cp.async 3-stage pipeline, ldmatrix
//     fragment loads, fused dcov epilogue + deterministic partial sums.
// ---------------------------------------------------------------------------
constexpr int NTILE  = DIM / 128;
constexpr int NPAIRS = NTILE * (NTILE + 1) / 2;   // 36
constexpr int BK     = 32;
constexpr int NITER  = MM / BK;                   // 16
constexpr int STAGES = 3;
constexpr int ROWP   = BK + 4;                    // 36 floats (144B) row stride
constexpr int STAGE_FLOATS = 128 * ROWP;          // 4608
constexpr int SMEM_BYTES = STAGES * 2 * STAGE_FLOATS * 4;  // 110592

__global__ __launch_bounds__(256, 2)
void syrk_dcov_mma(const float* __restrict__ x) {
    extern __shared__ float smem[];
    uint32_t sbase = smem_u32(smem);

    int tid  = threadIdx.x;
    int wid  = tid >> 5;
    int lane = tid & 31;
    int grp  = lane >> 2;
    int qid  = lane & 3;
    int wm   = wid & 3;     // warp M (32 rows)
    int wn   = wid >> 2;    // warp N (64 cols)

    int p = blockIdx.x, bi = 0;
    while (p >= NTILE - bi) { p -= NTILE - bi; bi++; }
    int bj = bi + p;
    int b = blockIdx.y;

    const float* Abase = x + ((size_t)b * DIM + bi * 128) * MM;
    const float* Bbase = x + ((size_t)b * DIM + bj * 128) * MM;

    // cp.async slots: 4 chunks of 16B per matrix per thread per stage
    const float* gA[4];
    const float* gB[4];
    uint32_t soff[4];
    #pragma unroll
    for (int q = 0; q < 4; q++) {
        int idx = tid + 256 * q;
        int row = idx >> 3;
        int c8  = idx & 7;
        gA[q] = Abase + (size_t)row * MM + c8 * 4;
        gB[q] = Bbase + (size_t)row * MM + c8 * 4;
        soff[q] = (uint32_t)(row * ROWP + c8 * 4) * 4u;
    }

    auto issue = [&](int s) {
        int buf = s % STAGES;
        int k0  = s * BK;
        uint32_t ab = sbase + (uint32_t)buf * (2 * STAGE_FLOATS * 4);
        uint32_t bb = ab + STAGE_FLOATS * 4;
        #pragma unroll
        for (int q = 0; q < 4; q++) {
            cp16(ab + soff[q], gA[q] + k0);
            cp16(bb + soff[q], gB[q] + k0);
        }
    };

    // ldmatrix per-thread byte offsets (stage-invariant):
    // A frag (mt): mats {a0,a1,a2,a3} = rows m0+(lane&15), col +4 floats for lane>=16
    uint32_t aoff[2];
    #pragma unroll
    for (int mt = 0; mt < 2; mt++)
        aoff[mt] = (uint32_t)(((wm * 32 + mt * 16 + (lane & 15)) * ROWP
                              + (lane >> 4) * 4) * 4);
    // B frag (pair of nt): mats {b0(nt),b1(nt),b0(nt+1),b1(nt+1)}
    uint32_t boff[4];
    #pragma unroll
    for (int pr = 0; pr < 4; pr++)
        boff[pr] = (uint32_t)(((wn * 64 + pr * 16 + ((lane >> 4) & 1) * 8 + (lane & 7)) * ROWP
                              + ((lane >> 3) & 1) * 4) * 4);

    float c[2][8][4] = {};

    issue(0); CP_COMMIT();
    issue(1); CP_COMMIT();

    for (int it = 0; it < NITER; it++) {
        CP_WAIT1();
        __syncthreads();

        if (it + 2 < NITER) issue(it + 2);
        CP_COMMIT();

        uint32_t sbA = sbase + (uint32_t)(it % STAGES) * (2 * STAGE_FLOATS * 4);
        uint32_t sbB = sbA + STAGE_FLOATS * 4;

        #pragma unroll
        for (int ks = 0; ks < 4; ks++) {
            uint32_t kb = ks * 32;   // 8 floats = 32 bytes
            uint32_t af[2][4];
            #pragma unroll
            for (int mt = 0; mt < 2; mt++)
                ldsm_x4(af[mt][0], af[mt][1], af[mt][2], af[mt][3], sbA + aoff[mt] + kb);
            uint32_t bf[8][2];
            #pragma unroll
            for (int pr = 0; pr < 4; pr++)
                ldsm_x4(bf[2*pr][0], bf[2*pr][1], bf[2*pr+1][0], bf[2*pr+1][1],
                        sbB + boff[pr] + kb);
            #pragma unroll
            for (int mt = 0; mt < 2; mt++)
                #pragma unroll
                for (int nt = 0; nt < 8; nt++)
                    mma_tf32(c[mt][nt], af[mt], bf[nt]);
        }
    }

    // ---------------- Epilogue ----------------
    int i0 = bi * 128, j0 = bj * 128;
    const float invM = 1.f / (float)MM;
    float* dcb = g_dcov + (size_t)b * DIM * DIM;
    bool offdiag = (bi != bj);
    const float* dgb = g_diag + b * DIM;

    float dj[8][2];
    #pragma unroll
    for (int nt = 0; nt < 8; nt++) {
        int j = j0 + wn * 64 + nt * 8 + 2 * qid;
        dj[nt][0] = dgb[j];
        dj[nt][1] = dgb[j + 1];
    }

    float rsum[2][2] = {};
    float csum[8][2] = {};

    #pragma unroll
    for (int mt = 0; mt < 2; mt++) {
        #pragma unroll
        for (int rr = 0; rr < 2; rr++) {
            int i = i0 + wm * 32 + mt * 16 + grp + rr * 8;
            float di = dgb[i - i0 + i0];
            #pragma unroll
            for (int nt = 0; nt < 8; nt++) {
                int j = j0 + wn * 64 + nt * 8 + 2 * qid;
                float dot0 = c[mt][nt][rr * 2 + 0];
                float dot1 = c[mt][nt][rr * 2 + 1];
                float d0 = (i == j)     ? 0.f : fmaxf(di + dj[nt][0] - dot0 * invM, 0.f);
                float d1 = (i == j + 1) ? 0.f : fmaxf(di + dj[nt][1] - dot1 * invM, 0.f);
                float v0 = exp2f(ALPHA * log2f(d0 + EPS));
                float v1 = exp2f(ALPHA * log2f(d1 + EPS));
                *reinterpret_cast<float2*>(dcb + (size_t)i * DIM + j) = make_float2(v0, v1);
                rsum[mt][rr] += v0 + v1;
                csum[nt][0]  += v0;
                csum[nt][1]  += v1;
            }
        }
    }

    #pragma unroll
    for (int mt = 0; mt < 2; mt++)
        #pragma unroll
        for (int rr = 0; rr < 2; rr++) {
            rsum[mt][rr] += __shfl_xor_sync(0xFFFFFFFFu, rsum[mt][rr], 1);
            rsum[mt][rr] += __shfl_xor_sync(0xFFFFFFFFu, rsum[mt][rr], 2);
        }
    #pragma unroll
    for (int nt = 0; nt < 8; nt++)
        #pragma unroll
        for (int h = 0; h < 2; h++) {
            csum[nt][h] += __shfl_xor_sync(0xFFFFFFFFu, csum[nt][h], 4);
            csum[nt][h] += __shfl_xor_sync(0xFFFFFFFFu, csum[nt][h], 8);
            csum[nt][h] += __shfl_xor_sync(0xFFFFFFFFu, csum[nt][h], 16);
        }

    __syncthreads();
    float* rbuf = smem;          // 256 floats
    float* cbuf = smem + 256;    // 512 floats
    if (qid == 0) {
        #pragma unroll
        for (int mt = 0; mt < 2; mt++)
            #pragma unroll
            for (int rr = 0; rr < 2; rr++)
                rbuf[wn * 128 + wm * 32 + mt * 16 + rr * 8 + grp] = rsum[mt][rr];
    }
    if (grp == 0) {
        #pragma unroll
        for (int nt = 0; nt < 8; nt++) {
            cbuf[wm * 128 + wn * 64 + nt * 8 + 2 * qid + 0] = csum[nt][0];
            cbuf[wm * 128 + wn * 64 + nt * 8 + 2 * qid + 1] = csum[nt][1];
        }
    }
    __syncthreads();

    if (tid < 128) {
        float rs = rbuf[tid] + rbuf[128 + tid];
        g_part[(((size_t)b * 8 + bi) * 8 + bj) * 128 + tid] = rs;
    } else if (offdiag) {
        int t = tid - 128;
        float cs = cbuf[t] + cbuf[128 + t] + cbuf[256 + t] + cbuf[384 + t];
        g_part[(((size_t)b * 8 + bj) * 8 + bi) * 128 + t] = cs;
    }
}

// ---------------------------------------------------------------------------
// K2: row means + total mean in one kernel. grid=B, block=1024.
// ---------------------------------------------------------------------------
__global__ void means_kernel() {
    int b = blockIdx.x;
    int i = threadIdx.x;          // 0..1023
    int ti = i >> 7;
    int ii = i & 127;
    float s = 0.f;
    #pragma unroll
    for (int tj = 0; tj < 8; tj++)
        s += g_part[(((size_t)b * 8 + ti) * 8 + tj) * 128 + ii];
    float m = s * (1.f / DIM);
    g_mean[b * DIM + i] = m;

    // block-reduce row means -> total mean
    __shared__ float sh[32];
    float t = m;
    #pragma unroll
    for (int off = 16; off > 0; off >>= 1)
        t += __shfl_down_sync(0xFFFFFFFFu, t, off);
    if ((i & 31) == 0) sh[i >> 5] = t;
    __syncthreads();
    if (i < 32) {
        float u = sh[i];
        #pragma unroll
        for (int off = 16; off > 0; off >>= 1)
            u += __shfl_down_sync(0xFFFFFFFFu, u, off);
        if (i == 0) g_tot[b] = u * (1.f / DIM);
    }
}

// ---------------------------------------------------------------------------
// K3: double-centering + triu extraction
// ---------------------------------------------------------------------------
__global__ void triu_kernel(float* __restrict__ out) {
    int i = blockIdx.x;
    int b = blockIdx.y;
    int L = DIM - i;
    size_t base = (size_t)b * OUT_PER_B + (size_t)i * DIM - (size_t)(i * (i - 1) / 2);
    const float* row = g_dcov + ((size_t)b * DIM + i) * DIM;
    float adj = g_tot[b] - g_mean[b * DIM + i];
    for (int q = threadIdx.x; q < L; q += blockDim.x) {
        int j = i + q;
        out[base + q] = row[j] - g_mean[b * DIM + j] + adj;
    }
}

// ---------------------------------------------------------------------------
extern "C" void kernel_launch(void* const* d_in, const int* in_sizes, int n_in,
                              void* d_out, int out_size) {
    const float* x = (const float*)d_in[0];
    float* out = (float*)d_out;

    static bool attr_set = false;
    if (!attr_set) {
        cudaFuncSetAttribute(syrk_dcov_mma,
                             cudaFuncAttributeMaxDynamicSharedMemorySize, SMEM_BYTES);
        attr_set = true;
    }

    diag_kernel<<<(B * DIM) / 8, 256>>>(x);
    syrk_dcov_mma<<<dim3(NPAIRS, B), 256, SMEM_BYTES>>>(x);
    means_kernel<<<B, 1024>>>();
    triu_kernel<<<dim3(DIM, B), 256>>>(out);
}

// round 7
// speedup vs baseline: 3.4588x; 1.1115x over previous
#include <cuda_runtime.h>
#include <cstdint>

// Problem constants
constexpr int B   = 32;
constexpr int DIM = 1024;
constexpr int MM  = 512;
constexpr int OUT_PER_B = DIM * (DIM + 1) / 2;    // 524800 = 8 * 65600
constexpr float ALPHA = 0.4f;
constexpr float EPS   = 1e-5f;

// Scratch
__device__ float g_dcov[(size_t)B * DIM * DIM];   // upper tiles only
__device__ float g_diag[B * DIM];
__device__ float g_part[B * 8 * 8 * 128];
__device__ float g_mean[B * DIM];
__device__ float g_tot[B];

// ---------------------------------------------------------------------------
__device__ __forceinline__ void mma_tf32(float* c, const uint32_t* a, const uint32_t* b) {
    asm volatile(
        "mma.sync.aligned.m16n8k8.row.col.f32.tf32.tf32.f32 "
        "{%0,%1,%2,%3}, {%4,%5,%6,%7}, {%8,%9}, {%0,%1,%2,%3};"
        : "+f"(c[0]), "+f"(c[1]), "+f"(c[2]), "+f"(c[3])
        : "r"(a[0]), "r"(a[1]), "r"(a[2]), "r"(a[3]), "r"(b[0]), "r"(b[1]));
}
__device__ __forceinline__ void ldsm_x4(uint32_t& r0, uint32_t& r1, uint32_t& r2,
                                        uint32_t& r3, uint32_t addr) {
    asm volatile("ldmatrix.sync.aligned.m8n8.x4.shared.b16 {%0,%1,%2,%3}, [%4];"
        : "=r"(r0), "=r"(r1), "=r"(r2), "=r"(r3) : "r"(addr));
}
__device__ __forceinline__ uint32_t smem_u32(const void* p) {
    uint32_t a;
    asm("{ .reg .u64 t; cvta.to.shared.u64 t, %1; cvt.u32.u64 %0, t; }" : "=r"(a) : "l"(p));
    return a;
}
__device__ __forceinline__ void cp16(uint32_t saddr, const void* g) {
    asm volatile("cp.async.cg.shared.global [%0], [%1], 16;" :: "r"(saddr), "l"(g));
}
#define CP_COMMIT() asm volatile("cp.async.commit_group;" ::: "memory")
#define CP_WAIT1()  asm volatile("cp.async.wait_group 1;" ::: "memory")

// ---------------------------------------------------------------------------
// K0: diag[b][i] = ||x_i||^2 / (2M)   (exact fp32)
// ---------------------------------------------------------------------------
__global__ void diag_kernel(const float* __restrict__ x) {
    int warp = (blockIdx.x * blockDim.x + threadIdx.x) >> 5;
    int lane = threadIdx.x & 31;
    if (warp >= B * DIM) return;
    const float4* row = reinterpret_cast<const float4*>(x + (size_t)warp * MM);
    float s = 0.f;
    #pragma unroll
    for (int k = 0; k < 4; k++) {
        float4 v = row[lane + 32 * k];
        s += v.x * v.x + v.y * v.y + v.z * v.z + v.w * v.w;
    }
    #pragma unroll
    for (int off = 16; off > 0; off >>= 1)
        s += __shfl_down_sync(0xFFFFFFFFu, s, off);
    if (lane == 0) g_diag[warp] = s * (1.f / (2.f * MM));
}

// ---------------------------------------------------------------------------
// K1: TF32 mma.sync SYRK, cp.async 3-stage pipeline, ldmatrix frags,
//     fused dcov epilogue + deterministic partial sums.
// ---------------------------------------------------------------------------
constexpr int NTILE  = DIM / 128;
constexpr int NPAIRS = NTILE * (NTILE + 1) / 2;   // 36
constexpr int BK     = 32;
constexpr int NITER  = MM / BK;                   // 16
constexpr int STAGES = 3;
constexpr int ROWP   = BK + 4;                    // 36 floats (144B) row stride
constexpr int STAGE_FLOATS = 128 * ROWP;
constexpr int SMEM_BYTES = STAGES * 2 * STAGE_FLOATS * 4;  // 110592

__global__ __launch_bounds__(256, 2)
void syrk_dcov_mma(const float* __restrict__ x) {
    extern __shared__ float smem[];
    uint32_t sbase = smem_u32(smem);

    int tid  = threadIdx.x;
    int wid  = tid >> 5;
    int lane = tid & 31;
    int grp  = lane >> 2;
    int qid  = lane & 3;
    int wm   = wid & 3;
    int wn   = wid >> 2;

    int p = blockIdx.x, bi = 0;
    while (p >= NTILE - bi) { p -= NTILE - bi; bi++; }
    int bj = bi + p;
    int b = blockIdx.y;

    const float* Abase = x + ((size_t)b * DIM + bi * 128) * MM;
    const float* Bbase = x + ((size_t)b * DIM + bj * 128) * MM;

    const float* gA[4];
    const float* gB[4];
    uint32_t soff[4];
    #pragma unroll
    for (int q = 0; q < 4; q++) {
        int idx = tid + 256 * q;
        int row = idx >> 3;
        int c8  = idx & 7;
        gA[q] = Abase + (size_t)row * MM + c8 * 4;
        gB[q] = Bbase + (size_t)row * MM + c8 * 4;
        soff[q] = (uint32_t)(row * ROWP + c8 * 4) * 4u;
    }

    auto issue = [&](int s) {
        int buf = s % STAGES;
        int k0  = s * BK;
        uint32_t ab = sbase + (uint32_t)buf * (2 * STAGE_FLOATS * 4);
        uint32_t bb = ab + STAGE_FLOATS * 4;
        #pragma unroll
        for (int q = 0; q < 4; q++) {
            cp16(ab + soff[q], gA[q] + k0);
            cp16(bb + soff[q], gB[q] + k0);
        }
    };

    uint32_t aoff[2];
    #pragma unroll
    for (int mt = 0; mt < 2; mt++)
        aoff[mt] = (uint32_t)(((wm * 32 + mt * 16 + (lane & 15)) * ROWP
                              + (lane >> 4) * 4) * 4);
    uint32_t boff[4];
    #pragma unroll
    for (int pr = 0; pr < 4; pr++)
        boff[pr] = (uint32_t)(((wn * 64 + pr * 16 + ((lane >> 4) & 1) * 8 + (lane & 7)) * ROWP
                              + ((lane >> 3) & 1) * 4) * 4);

    float c[2][8][4] = {};

    issue(0); CP_COMMIT();
    issue(1); CP_COMMIT();

    for (int it = 0; it < NITER; it++) {
        CP_WAIT1();
        __syncthreads();

        if (it + 2 < NITER) issue(it + 2);
        CP_COMMIT();

        uint32_t sbA = sbase + (uint32_t)(it % STAGES) * (2 * STAGE_FLOATS * 4);
        uint32_t sbB = sbA + STAGE_FLOATS * 4;

        #pragma unroll
        for (int ks = 0; ks < 4; ks++) {
            uint32_t kb = ks * 32;
            uint32_t af[2][4];
            #pragma unroll
            for (int mt = 0; mt < 2; mt++)
                ldsm_x4(af[mt][0], af[mt][1], af[mt][2], af[mt][3], sbA + aoff[mt] + kb);
            uint32_t bf[8][2];
            #pragma unroll
            for (int pr = 0; pr < 4; pr++)
                ldsm_x4(bf[2*pr][0], bf[2*pr][1], bf[2*pr+1][0], bf[2*pr+1][1],
                        sbB + boff[pr] + kb);
            #pragma unroll
            for (int mt = 0; mt < 2; mt++)
                #pragma unroll
                for (int nt = 0; nt < 8; nt++)
                    mma_tf32(c[mt][nt], af[mt], bf[nt]);
        }
    }

    // ---------------- Epilogue ----------------
    int i0 = bi * 128, j0 = bj * 128;
    const float invM = 1.f / (float)MM;
    float* dcb = g_dcov + (size_t)b * DIM * DIM;
    bool offdiag = (bi != bj);
    const float* dgb = g_diag + b * DIM;

    float dj[8][2];
    #pragma unroll
    for (int nt = 0; nt < 8; nt++) {
        int j = j0 + wn * 64 + nt * 8 + 2 * qid;
        dj[nt][0] = dgb[j];
        dj[nt][1] = dgb[j + 1];
    }

    float rsum[2][2] = {};
    float csum[8][2] = {};

    #pragma unroll
    for (int mt = 0; mt < 2; mt++) {
        #pragma unroll
        for (int rr = 0; rr < 2; rr++) {
            int i = i0 + wm * 32 + mt * 16 + grp + rr * 8;
            float di = dgb[i - i0 + i0];
            #pragma unroll
            for (int nt = 0; nt < 8; nt++) {
                int j = j0 + wn * 64 + nt * 8 + 2 * qid;
                float dot0 = c[mt][nt][rr * 2 + 0];
                float dot1 = c[mt][nt][rr * 2 + 1];
                float d0 = (i == j)     ? 0.f : fmaxf(di + dj[nt][0] - dot0 * invM, 0.f);
                float d1 = (i == j + 1) ? 0.f : fmaxf(di + dj[nt][1] - dot1 * invM, 0.f);
                float v0 = exp2f(ALPHA * log2f(d0 + EPS));
                float v1 = exp2f(ALPHA * log2f(d1 + EPS));
                *reinterpret_cast<float2*>(dcb + (size_t)i * DIM + j) = make_float2(v0, v1);
                rsum[mt][rr] += v0 + v1;
                csum[nt][0]  += v0;
                csum[nt][1]  += v1;
            }
        }
    }

    #pragma unroll
    for (int mt = 0; mt < 2; mt++)
        #pragma unroll
        for (int rr = 0; rr < 2; rr++) {
            rsum[mt][rr] += __shfl_xor_sync(0xFFFFFFFFu, rsum[mt][rr], 1);
            rsum[mt][rr] += __shfl_xor_sync(0xFFFFFFFFu, rsum[mt][rr], 2);
        }
    #pragma unroll
    for (int nt = 0; nt < 8; nt++)
        #pragma unroll
        for (int h = 0; h < 2; h++) {
            csum[nt][h] += __shfl_xor_sync(0xFFFFFFFFu, csum[nt][h], 4);
            csum[nt][h] += __shfl_xor_sync(0xFFFFFFFFu, csum[nt][h], 8);
            csum[nt][h] += __shfl_xor_sync(0xFFFFFFFFu, csum[nt][h], 16);
        }

    __syncthreads();
    float* rbuf = smem;
    float* cbuf = smem + 256;
    if (qid == 0) {
        #pragma unroll
        for (int mt = 0; mt < 2; mt++)
            #pragma unroll
            for (int rr = 0; rr < 2; rr++)
                rbuf[wn * 128 + wm * 32 + mt * 16 + rr * 8 + grp] = rsum[mt][rr];
    }
    if (grp == 0) {
        #pragma unroll
        for (int nt = 0; nt < 8; nt++) {
            cbuf[wm * 128 + wn * 64 + nt * 8 + 2 * qid + 0] = csum[nt][0];
            cbuf[wm * 128 + wn * 64 + nt * 8 + 2 * qid + 1] = csum[nt][1];
        }
    }
    __syncthreads();

    if (tid < 128) {
        float rs = rbuf[tid] + rbuf[128 + tid];
        g_part[(((size_t)b * 8 + bi) * 8 + bj) * 128 + tid] = rs;
    } else if (offdiag) {
        int t = tid - 128;
        float cs = cbuf[t] + cbuf[128 + t] + cbuf[256 + t] + cbuf[384 + t];
        g_part[(((size_t)b * 8 + bj) * 8 + bi) * 128 + t] = cs;
    }
}

// ---------------------------------------------------------------------------
// K2: row means + total mean. grid=B, block=1024.
// ---------------------------------------------------------------------------
__global__ void means_kernel() {
    int b = blockIdx.x;
    int i = threadIdx.x;
    int ti = i >> 7;
    int ii = i & 127;
    float s = 0.f;
    #pragma unroll
    for (int tj = 0; tj < 8; tj++)
        s += g_part[(((size_t)b * 8 + ti) * 8 + tj) * 128 + ii];
    float m = s * (1.f / DIM);
    g_mean[b * DIM + i] = m;

    __shared__ float sh[32];
    float t = m;
    #pragma unroll
    for (int off = 16; off > 0; off >>= 1)
        t += __shfl_down_sync(0xFFFFFFFFu, t, off);
    if ((i & 31) == 0) sh[i >> 5] = t;
    __syncthreads();
    if (i < 32) {
        float u = sh[i];
        #pragma unroll
        for (int off = 16; off > 0; off >>= 1)
            u += __shfl_down_sync(0xFFFFFFFFu, u, off);
        if (i == 0) g_tot[b] = u * (1.f / DIM);
    }
}

// ---------------------------------------------------------------------------
// K3: flat triu: 8 consecutive packed outputs per thread, float4 stores.
// off(i) = i*(2049-i)/2;  i from flat f via exact-fp32 sqrt + fixup.
// ---------------------------------------------------------------------------
__device__ __forceinline__ int triu_off(int i) { return i * (2 * DIM + 1 - i) / 2; }

constexpr int TRIU_TPB  = 65600;               // threads per batch (OUT_PER_B/8)
constexpr int TRIU_BLKS = (TRIU_TPB + 255) / 256;  // 257

__global__ void triu_flat_kernel(float* __restrict__ out) {
    int b = blockIdx.y;
    int t = blockIdx.x * 256 + threadIdx.x;
    if (t >= TRIU_TPB) return;
    int f = t * 8;

    // analytic row index: i = floor((2049 - sqrt(2049^2 - 8f)) / 2)
    float s = sqrtf((float)(4198401 - 8 * f));
    int i = (int)((2049.0f - s) * 0.5f);
    if (i > DIM - 1) i = DIM - 1;
    if (i < 0) i = 0;
    while (i > 0 && triu_off(i) > f) i--;
    while (i < DIM - 1 && triu_off(i + 1) <= f) i++;

    int off_i = triu_off(i);
    int next  = off_i + (DIM - i);

    const float* mean = g_mean + b * DIM;
    const float  tot  = g_tot[b];
    const float* dc   = g_dcov + (size_t)b * DIM * DIM;
    float adj = tot - mean[i];
    const float* rowp = dc + (size_t)i * DIM;

    float v[8];
    #pragma unroll
    for (int e = 0; e < 8; e++) {
        int fe = f + e;
        while (fe >= next) {            // row crossing (rare; walks 1+ rows)
            i++;
            off_i = next;
            next += DIM - i;
            adj = tot - mean[i];
            rowp = dc + (size_t)i * DIM;
        }
        int j = i + (fe - off_i);
        v[e] = rowp[j] - mean[j] + adj;
    }

    float4* o = reinterpret_cast<float4*>(out + (size_t)b * OUT_PER_B + f);
    o[0] = make_float4(v[0], v[1], v[2], v[3]);
    o[1] = make_float4(v[4], v[5], v[6], v[7]);
}

// ---------------------------------------------------------------------------
extern "C" void kernel_launch(void* const* d_in, const int* in_sizes, int n_in,
                              void* d_out, int out_size) {
    const float* x = (const float*)d_in[0];
    float* out = (float*)d_out;

    static bool attr_set = false;
    if (!attr_set) {
        cudaFuncSetAttribute(syrk_dcov_mma,
                             cudaFuncAttributeMaxDynamicSharedMemorySize, SMEM_BYTES);
        attr_set = true;
    }

    diag_kernel<<<(B * DIM) / 8, 256>>>(x);
    syrk_dcov_mma<<<dim3(NPAIRS, B), 256, SMEM_BYTES>>>(x);
    means_kernel<<<B, 1024>>>();
    triu_flat_kernel<<<dim3(TRIU_BLKS, B), 256>>>(out);
}

// round 8
// speedup vs baseline: 3.6989x; 1.0694x over previous
#include <cuda_runtime.h>
#include <cstdint>

// Problem constants
constexpr int B   = 32;
constexpr int DIM = 1024;
constexpr int MM  = 512;
constexpr int OUT_PER_B = DIM * (DIM + 1) / 2;    // 524800
constexpr float ALPHA = 0.4f;
constexpr float EPS   = 1e-5f;

// Scratch
__device__ float g_dcov[(size_t)B * DIM * DIM];   // upper tiles only
__device__ float g_part[B * 8 * 8 * 128];
__device__ float g_mean[B * DIM];
__device__ float g_tot[B];

// ---------------------------------------------------------------------------
__device__ __forceinline__ void mma_tf32(float* c, const uint32_t* a, const uint32_t* b) {
    asm volatile(
        "mma.sync.aligned.m16n8k8.row.col.f32.tf32.tf32.f32 "
        "{%0,%1,%2,%3}, {%4,%5,%6,%7}, {%8,%9}, {%0,%1,%2,%3};"
        : "+f"(c[0]), "+f"(c[1]), "+f"(c[2]), "+f"(c[3])
        : "r"(a[0]), "r"(a[1]), "r"(a[2]), "r"(a[3]), "r"(b[0]), "r"(b[1]));
}
__device__ __forceinline__ void ldsm_x4(uint32_t& r0, uint32_t& r1, uint32_t& r2,
                                        uint32_t& r3, uint32_t addr) {
    asm volatile("ldmatrix.sync.aligned.m8n8.x4.shared.b16 {%0,%1,%2,%3}, [%4];"
        : "=r"(r0), "=r"(r1), "=r"(r2), "=r"(r3) : "r"(addr));
}
__device__ __forceinline__ uint32_t smem_u32(const void* p) {
    uint32_t a;
    asm("{ .reg .u64 t; cvta.to.shared.u64 t, %1; cvt.u32.u64 %0, t; }" : "=r"(a) : "l"(p));
    return a;
}
__device__ __forceinline__ void cp16(uint32_t saddr, const void* g) {
    asm volatile("cp.async.cg.shared.global [%0], [%1], 16;" :: "r"(saddr), "l"(g));
}
#define CP_COMMIT() asm volatile("cp.async.commit_group;" ::: "memory")
#define CP_WAIT1()  asm volatile("cp.async.wait_group 1;" ::: "memory")

// ---------------------------------------------------------------------------
// K1: TF32 mma.sync SYRK, cp.async 3-stage pipeline, ldmatrix frags,
//     fused row-norm (diag) accumulation from smem, fused dcov epilogue
//     + deterministic partial sums.
// ---------------------------------------------------------------------------
constexpr int NTILE  = DIM / 128;
constexpr int NPAIRS = NTILE * (NTILE + 1) / 2;   // 36
constexpr int BK     = 32;
constexpr int NITER  = MM / BK;                   // 16
constexpr int STAGES = 3;
constexpr int ROWP   = BK + 4;                    // 36 floats (144B) row stride
constexpr int STAGE_FLOATS = 128 * ROWP;
constexpr int SMEM_BYTES = STAGES * 2 * STAGE_FLOATS * 4;  // 110592

__global__ __launch_bounds__(256, 2)
void syrk_dcov_mma(const float* __restrict__ x) {
    extern __shared__ float smem[];
    uint32_t sbase = smem_u32(smem);

    int tid  = threadIdx.x;
    int wid  = tid >> 5;
    int lane = tid & 31;
    int grp  = lane >> 2;
    int qid  = lane & 3;
    int wm   = wid & 3;
    int wn   = wid >> 2;

    int p = blockIdx.x, bi = 0;
    while (p >= NTILE - bi) { p -= NTILE - bi; bi++; }
    int bj = bi + p;
    int b = blockIdx.y;

    const float* Abase = x + ((size_t)b * DIM + bi * 128) * MM;
    const float* Bbase = x + ((size_t)b * DIM + bj * 128) * MM;

    const float* gA[4];
    const float* gB[4];
    uint32_t soff[4];
    #pragma unroll
    for (int q = 0; q < 4; q++) {
        int idx = tid + 256 * q;
        int row = idx >> 3;
        int c8  = idx & 7;
        gA[q] = Abase + (size_t)row * MM + c8 * 4;
        gB[q] = Bbase + (size_t)row * MM + c8 * 4;
        soff[q] = (uint32_t)(row * ROWP + c8 * 4) * 4u;
    }

    auto issue = [&](int s) {
        int buf = s % STAGES;
        int k0  = s * BK;
        uint32_t ab = sbase + (uint32_t)buf * (2 * STAGE_FLOATS * 4);
        uint32_t bb = ab + STAGE_FLOATS * 4;
        #pragma unroll
        for (int q = 0; q < 4; q++) {
            cp16(ab + soff[q], gA[q] + k0);
            cp16(bb + soff[q], gB[q] + k0);
        }
    };

    uint32_t aoff[2];
    #pragma unroll
    for (int mt = 0; mt < 2; mt++)
        aoff[mt] = (uint32_t)(((wm * 32 + mt * 16 + (lane & 15)) * ROWP
                              + (lane >> 4) * 4) * 4);
    uint32_t boff[4];
    #pragma unroll
    for (int pr = 0; pr < 4; pr++)
        boff[pr] = (uint32_t)(((wn * 64 + pr * 16 + ((lane >> 4) & 1) * 8 + (lane & 7)) * ROWP
                              + ((lane >> 3) & 1) * 4) * 4);

    // fused norm: thread t accumulates ||row||^2 for A row (t<128) / B row (t-128)
    int nr = tid & 127;
    int nrsel = (tid < 128) ? 0 : 1;   // 0 = A buffer, 1 = B buffer
    float norm = 0.f;

    float c[2][8][4] = {};

    issue(0); CP_COMMIT();
    issue(1); CP_COMMIT();

    for (int it = 0; it < NITER; it++) {
        CP_WAIT1();
        __syncthreads();

        if (it + 2 < NITER) issue(it + 2);
        CP_COMMIT();

        uint32_t sbA = sbase + (uint32_t)(it % STAGES) * (2 * STAGE_FLOATS * 4);
        uint32_t sbB = sbA + STAGE_FLOATS * 4;

        // norm accumulation from smem (same sync window as fragment loads)
        {
            const float4* nrow = reinterpret_cast<const float4*>(
                smem + (it % STAGES) * (2 * STAGE_FLOATS) + nrsel * STAGE_FLOATS
                     + nr * ROWP);
            #pragma unroll
            for (int q8 = 0; q8 < 8; q8++) {
                float4 v = nrow[q8];
                norm += v.x * v.x + v.y * v.y + v.z * v.z + v.w * v.w;
            }
        }

        #pragma unroll
        for (int ks = 0; ks < 4; ks++) {
            uint32_t kb = ks * 32;
            uint32_t af[2][4];
            #pragma unroll
            for (int mt = 0; mt < 2; mt++)
                ldsm_x4(af[mt][0], af[mt][1], af[mt][2], af[mt][3], sbA + aoff[mt] + kb);
            uint32_t bf[8][2];
            #pragma unroll
            for (int pr = 0; pr < 4; pr++)
                ldsm_x4(bf[2*pr][0], bf[2*pr][1], bf[2*pr+1][0], bf[2*pr+1][1],
                        sbB + boff[pr] + kb);
            #pragma unroll
            for (int mt = 0; mt < 2; mt++)
                #pragma unroll
                for (int nt = 0; nt < 8; nt++)
                    mma_tf32(c[mt][nt], af[mt], bf[nt]);
        }
    }

    // publish norms: dn[0..127] = A-row diags, dn[128..255] = B-row diags
    __syncthreads();
    float* dn = smem + 768;
    dn[tid] = norm * (1.f / (2.f * MM));
    __syncthreads();

    // ---------------- Epilogue ----------------
    int i0 = bi * 128, j0 = bj * 128;
    const float invM = 1.f / (float)MM;
    float* dcb = g_dcov + (size_t)b * DIM * DIM;
    bool offdiag = (bi != bj);

    float dj[8][2];
    #pragma unroll
    for (int nt = 0; nt < 8; nt++) {
        int jl = wn * 64 + nt * 8 + 2 * qid;
        dj[nt][0] = dn[128 + jl];
        dj[nt][1] = dn[128 + jl + 1];
    }

    float rsum[2][2] = {};
    float csum[8][2] = {};

    #pragma unroll
    for (int mt = 0; mt < 2; mt++) {
        #pragma unroll
        for (int rr = 0; rr < 2; rr++) {
            int il = wm * 32 + mt * 16 + grp + rr * 8;
            int i = i0 + il;
            float di = dn[il];
            #pragma unroll
            for (int nt = 0; nt < 8; nt++) {
                int j = j0 + wn * 64 + nt * 8 + 2 * qid;
                float dot0 = c[mt][nt][rr * 2 + 0];
                float dot1 = c[mt][nt][rr * 2 + 1];
                float d0 = (i == j)     ? 0.f : fmaxf(di + dj[nt][0] - dot0 * invM, 0.f);
                float d1 = (i == j + 1) ? 0.f : fmaxf(di + dj[nt][1] - dot1 * invM, 0.f);
                float v0 = exp2f(ALPHA * log2f(d0 + EPS));
                float v1 = exp2f(ALPHA * log2f(d1 + EPS));
                *reinterpret_cast<float2*>(dcb + (size_t)i * DIM + j) = make_float2(v0, v1);
                rsum[mt][rr] += v0 + v1;
                csum[nt][0]  += v0;
                csum[nt][1]  += v1;
            }
        }
    }

    #pragma unroll
    for (int mt = 0; mt < 2; mt++)
        #pragma unroll
        for (int rr = 0; rr < 2; rr++) {
            rsum[mt][rr] += __shfl_xor_sync(0xFFFFFFFFu, rsum[mt][rr], 1);
            rsum[mt][rr] += __shfl_xor_sync(0xFFFFFFFFu, rsum[mt][rr], 2);
        }
    #pragma unroll
    for (int nt = 0; nt < 8; nt++)
        #pragma unroll
        for (int h = 0; h < 2; h++) {
            csum[nt][h] += __shfl_xor_sync(0xFFFFFFFFu, csum[nt][h], 4);
            csum[nt][h] += __shfl_xor_sync(0xFFFFFFFFu, csum[nt][h], 8);
            csum[nt][h] += __shfl_xor_sync(0xFFFFFFFFu, csum[nt][h], 16);
        }

    __syncthreads();
    float* rbuf = smem;          // [0..256)
    float* cbuf = smem + 256;    // [256..768)
    if (qid == 0) {
        #pragma unroll
        for (int mt = 0; mt < 2; mt++)
            #pragma unroll
            for (int rr = 0; rr < 2; rr++)
                rbuf[wn * 128 + wm * 32 + mt * 16 + rr * 8 + grp] = rsum[mt][rr];
    }
    if (grp == 0) {
        #pragma unroll
        for (int nt = 0; nt < 8; nt++) {
            cbuf[wm * 128 + wn * 64 + nt * 8 + 2 * qid + 0] = csum[nt][0];
            cbuf[wm * 128 + wn * 64 + nt * 8 + 2 * qid + 1] = csum[nt][1];
        }
    }
    __syncthreads();

    if (tid < 128) {
        float rs = rbuf[tid] + rbuf[128 + tid];
        g_part[(((size_t)b * 8 + bi) * 8 + bj) * 128 + tid] = rs;
    } else if (offdiag) {
        int t = tid - 128;
        float cs = cbuf[t] + cbuf[128 + t] + cbuf[256 + t] + cbuf[384 + t];
        g_part[(((size_t)b * 8 + bj) * 8 + bi) * 128 + t] = cs;
    }
}

// ---------------------------------------------------------------------------
// K2: row means + total mean. grid=B, block=1024.
// ---------------------------------------------------------------------------
__global__ void means_kernel() {
    int b = blockIdx.x;
    int i = threadIdx.x;
    int ti = i >> 7;
    int ii = i & 127;
    float s = 0.f;
    #pragma unroll
    for (int tj = 0; tj < 8; tj++)
        s += g_part[(((size_t)b * 8 + ti) * 8 + tj) * 128 + ii];
    float m = s * (1.f / DIM);
    g_mean[b * DIM + i] = m;

    __shared__ float sh[32];
    float t = m;
    #pragma unroll
    for (int off = 16; off > 0; off >>= 1)
        t += __shfl_down_sync(0xFFFFFFFFu, t, off);
    if ((i & 31) == 0) sh[i >> 5] = t;
    __syncthreads();
    if (i < 32) {
        float u = sh[i];
        #pragma unroll
        for (int off = 16; off > 0; off >>= 1)
            u += __shfl_down_sync(0xFFFFFFFFu, u, off);
        if (i == 0) g_tot[b] = u * (1.f / DIM);
    }
}

// ---------------------------------------------------------------------------
// K3: warp-per-row triu. All loads/stores lane-contiguous.
// grid (DIM/8, B), block 256; warp w handles row 8*blk + w.
// ---------------------------------------------------------------------------
__device__ __forceinline__ long long triu_off(int i) {
    return (long long)i * (2 * DIM + 1 - i) / 2;
}

__global__ void triu_rows_kernel(float* __restrict__ out) {
    int b = blockIdx.y;
    int i = blockIdx.x * 8 + (threadIdx.x >> 5);
    int lane = threadIdx.x & 31;
    const float* row  = g_dcov + ((size_t)b * DIM + i) * DIM;
    const float* mean = g_mean + b * DIM;
    float adj = g_tot[b] - mean[i];
    long long base = (long long)b * OUT_PER_B + triu_off(i) - i;   // out idx = base + j
    for (int j = i + lane; j < DIM; j += 32)
        out[base + j] = row[j] - mean[j] + adj;
}

// ---------------------------------------------------------------------------
extern "C" void kernel_launch(void* const* d_in, const int* in_sizes, int n_in,
                              void* d_out, int out_size) {
    const float* x = (const float*)d_in[0];
    float* out = (float*)d_out;

    static bool attr_set = false;
    if (!attr_set) {
        cudaFuncSetAttribute(syrk_dcov_mma,
                             cudaFuncAttributeMaxDynamicSharedMemorySize, SMEM_BYTES);
        attr_set = true;
    }

    syrk_dcov_mma<<<dim3(NPAIRS, B), 256, SMEM_BYTES>>>(x);
    means_kernel<<<B, 1024>>>();
    triu_rows_kernel<<<dim3(DIM / 8, B), 256>>>(out);
}

// round 9
// speedup vs baseline: 3.7217x; 1.0061x over previous
#include <cuda_runtime.h>
#include <cstdint>

// Problem constants
constexpr int B   = 32;
constexpr int DIM = 1024;
constexpr int MM  = 512;
constexpr int OUT_PER_B = DIM * (DIM + 1) / 2;    // 524800
constexpr float ALPHA = 0.4f;
constexpr float EPS   = 1e-5f;

// Scratch
__device__ float g_dcov[(size_t)B * DIM * DIM];   // upper tiles only
__device__ float g_part[B * 8 * 8 * 128];
__device__ float g_mean[B * DIM];
__device__ float g_tot[B];

// ---------------------------------------------------------------------------
__device__ __forceinline__ void mma_tf32(float* c, const uint32_t* a, const uint32_t* b) {
    asm volatile(
        "mma.sync.aligned.m16n8k8.row.col.f32.tf32.tf32.f32 "
        "{%0,%1,%2,%3}, {%4,%5,%6,%7}, {%8,%9}, {%0,%1,%2,%3};"
        : "+f"(c[0]), "+f"(c[1]), "+f"(c[2]), "+f"(c[3])
        : "r"(a[0]), "r"(a[1]), "r"(a[2]), "r"(a[3]), "r"(b[0]), "r"(b[1]));
}
__device__ __forceinline__ void ldsm_x4(uint32_t& r0, uint32_t& r1, uint32_t& r2,
                                        uint32_t& r3, uint32_t addr) {
    asm volatile("ldmatrix.sync.aligned.m8n8.x4.shared.b16 {%0,%1,%2,%3}, [%4];"
        : "=r"(r0), "=r"(r1), "=r"(r2), "=r"(r3) : "r"(addr));
}
__device__ __forceinline__ uint32_t smem_u32(const void* p) {
    uint32_t a;
    asm("{ .reg .u64 t; cvta.to.shared.u64 t, %1; cvt.u32.u64 %0, t; }" : "=r"(a) : "l"(p));
    return a;
}
__device__ __forceinline__ void cp16(uint32_t saddr, const void* g) {
    asm volatile("cp.async.cg.shared.global [%0], [%1], 16;" :: "r"(saddr), "l"(g));
}
#define CP_COMMIT() asm volatile("cp.async.commit_group;" ::: "memory")
#define CP_WAIT1()  asm volatile("cp.async.wait_group 1;" ::: "memory")

// ---------------------------------------------------------------------------
// K1: TF32 mma.sync SYRK, cp.async 3-stage pipeline, ldmatrix frags with
//     immediate-offset addressing (low reg pressure), fused row-norm,
//     fused dcov epilogue + deterministic partial sums.
// ---------------------------------------------------------------------------
constexpr int NTILE  = DIM / 128;
constexpr int NPAIRS = NTILE * (NTILE + 1) / 2;   // 36
constexpr int BK     = 32;
constexpr int NITER  = MM / BK;                   // 16
constexpr int STAGES = 3;
constexpr int ROWP   = BK + 4;                    // 36 floats (144B) row stride
constexpr int STAGE_FLOATS = 128 * ROWP;
constexpr int STAGE_BYTES  = STAGE_FLOATS * 4;
constexpr int SMEM_BYTES = STAGES * 2 * STAGE_BYTES;  // 110592

// constant strides (immediates)
constexpr int GQ_STEP   = 32 * MM;          // elements between q-slots in gmem
constexpr int SQ_STEP   = 32 * ROWP * 4;    // bytes between q-slots in smem (4608)
constexpr int FRAG_STEP = 16 * ROWP * 4;    // bytes per 16 smem rows (2304)

__global__ __launch_bounds__(256, 2)
void syrk_dcov_mma(const float* __restrict__ x) {
    extern __shared__ float smem[];
    uint32_t sbase = smem_u32(smem);

    int tid  = threadIdx.x;
    int wid  = tid >> 5;
    int lane = tid & 31;
    int grp  = lane >> 2;
    int qid  = lane & 3;
    int wm   = wid & 3;
    int wn   = wid >> 2;

    int p = blockIdx.x, bi = 0;
    while (p >= NTILE - bi) { p -= NTILE - bi; bi++; }
    int bj = bi + p;
    int b = blockIdx.y;

    // single base pointers; q-slots are immediate offsets
    const float* baseA = x + ((size_t)b * DIM + bi * 128) * MM
                           + (size_t)(tid >> 3) * MM + (tid & 7) * 4;
    const float* baseB = x + ((size_t)b * DIM + bj * 128) * MM
                           + (size_t)(tid >> 3) * MM + (tid & 7) * 4;
    uint32_t soff0 = (uint32_t)(((tid >> 3) * ROWP + (tid & 7) * 4) * 4);

    auto issue = [&](int s) {
        uint32_t ab = sbase + (uint32_t)(s % STAGES) * (2 * STAGE_BYTES) + soff0;
        uint32_t bb = ab + STAGE_BYTES;
        const float* ga = baseA + s * BK;
        const float* gb = baseB + s * BK;
        #pragma unroll
        for (int q = 0; q < 4; q++) {
            cp16(ab + q * SQ_STEP, ga + q * GQ_STEP);
            cp16(bb + q * SQ_STEP, gb + q * GQ_STEP);
        }
    };

    // ldmatrix base offsets (single regs; mt/pr steps are immediates)
    uint32_t aoff0 = (uint32_t)(((wm * 32 + (lane & 15)) * ROWP + (lane >> 4) * 4) * 4);
    uint32_t boff0 = (uint32_t)(((wn * 64 + ((lane >> 4) & 1) * 8 + (lane & 7)) * ROWP
                                + ((lane >> 3) & 1) * 4) * 4);

    // fused norm: thread t accumulates ||row||^2 for A row (t<128) / B row (t-128)
    uint32_t normoff = (uint32_t)((tid < 128 ? 0 : STAGE_FLOATS) + (tid & 127) * ROWP);
    float norm = 0.f;

    float c[2][8][4] = {};

    issue(0); CP_COMMIT();
    issue(1); CP_COMMIT();

    for (int it = 0; it < NITER; it++) {
        CP_WAIT1();
        __syncthreads();

        if (it + 2 < NITER) issue(it + 2);
        CP_COMMIT();

        uint32_t sbA = sbase + (uint32_t)(it % STAGES) * (2 * STAGE_BYTES);
        uint32_t sbB = sbA + STAGE_BYTES;

        // norm accumulation from smem
        {
            const float4* nrow = reinterpret_cast<const float4*>(
                smem + (it % STAGES) * (2 * STAGE_FLOATS) + normoff);
            #pragma unroll
            for (int q8 = 0; q8 < 8; q8++) {
                float4 v = nrow[q8];
                norm += v.x * v.x + v.y * v.y + v.z * v.z + v.w * v.w;
            }
        }

        uint32_t aA = sbA + aoff0;
        uint32_t aB = sbB + boff0;

        #pragma unroll
        for (int ks = 0; ks < 4; ks++) {
            uint32_t kb = ks * 32;
            uint32_t af[2][4];
            #pragma unroll
            for (int mt = 0; mt < 2; mt++)
                ldsm_x4(af[mt][0], af[mt][1], af[mt][2], af[mt][3],
                        aA + mt * FRAG_STEP + kb);
            uint32_t bf[8][2];
            #pragma unroll
            for (int pr = 0; pr < 4; pr++)
                ldsm_x4(bf[2*pr][0], bf[2*pr][1], bf[2*pr+1][0], bf[2*pr+1][1],
                        aB + pr * FRAG_STEP + kb);
            #pragma unroll
            for (int mt = 0; mt < 2; mt++)
                #pragma unroll
                for (int nt = 0; nt < 8; nt++)
                    mma_tf32(c[mt][nt], af[mt], bf[nt]);
        }
    }

    // publish norms: dn[0..127] = A-row diags, dn[128..255] = B-row diags
    __syncthreads();
    float* dn = smem + 768;
    dn[tid] = norm * (1.f / (2.f * MM));
    __syncthreads();

    // ---------------- Epilogue ----------------
    int i0 = bi * 128, j0 = bj * 128;
    const float invM = 1.f / (float)MM;
    float* dcb = g_dcov + (size_t)b * DIM * DIM;
    bool offdiag = (bi != bj);

    float dj[8][2];
    #pragma unroll
    for (int nt = 0; nt < 8; nt++) {
        int jl = wn * 64 + nt * 8 + 2 * qid;
        dj[nt][0] = dn[128 + jl];
        dj[nt][1] = dn[128 + jl + 1];
    }

    float rsum[2][2] = {};
    float csum[8][2] = {};

    #pragma unroll
    for (int mt = 0; mt < 2; mt++) {
        #pragma unroll
        for (int rr = 0; rr < 2; rr++) {
            int il = wm * 32 + mt * 16 + grp + rr * 8;
            int i = i0 + il;
            float di = dn[il];
            #pragma unroll
            for (int nt = 0; nt < 8; nt++) {
                int j = j0 + wn * 64 + nt * 8 + 2 * qid;
                float dot0 = c[mt][nt][rr * 2 + 0];
                float dot1 = c[mt][nt][rr * 2 + 1];
                float d0 = (i == j)     ? 0.f : fmaxf(di + dj[nt][0] - dot0 * invM, 0.f);
                float d1 = (i == j + 1) ? 0.f : fmaxf(di + dj[nt][1] - dot1 * invM, 0.f);
                float v0 = exp2f(ALPHA * log2f(d0 + EPS));
                float v1 = exp2f(ALPHA * log2f(d1 + EPS));
                *reinterpret_cast<float2*>(dcb + (size_t)i * DIM + j) = make_float2(v0, v1);
                rsum[mt][rr] += v0 + v1;
                csum[nt][0]  += v0;
                csum[nt][1]  += v1;
            }
        }
    }

    #pragma unroll
    for (int mt = 0; mt < 2; mt++)
        #pragma unroll
        for (int rr = 0; rr < 2; rr++) {
            rsum[mt][rr] += __shfl_xor_sync(0xFFFFFFFFu, rsum[mt][rr], 1);
            rsum[mt][rr] += __shfl_xor_sync(0xFFFFFFFFu, rsum[mt][rr], 2);
        }
    #pragma unroll
    for (int nt = 0; nt < 8; nt++)
        #pragma unroll
        for (int h = 0; h < 2; h++) {
            csum[nt][h] += __shfl_xor_sync(0xFFFFFFFFu, csum[nt][h], 4);
            csum[nt][h] += __shfl_xor_sync(0xFFFFFFFFu, csum[nt][h], 8);
            csum[nt][h] += __shfl_xor_sync(0xFFFFFFFFu, csum[nt][h], 16);
        }

    __syncthreads();
    float* rbuf = smem;          // [0..256)
    float* cbuf = smem + 256;    // [256..768)
    if (qid == 0) {
        #pragma unroll
        for (int mt = 0; mt < 2; mt++)
            #pragma unroll
            for (int rr = 0; rr < 2; rr++)
                rbuf[wn * 128 + wm * 32 + mt * 16 + rr * 8 + grp] = rsum[mt][rr];
    }
    if (grp == 0) {
        #pragma unroll
        for (int nt = 0; nt < 8; nt++) {
            cbuf[wm * 128 + wn * 64 + nt * 8 + 2 * qid + 0] = csum[nt][0];
            cbuf[wm * 128 + wn * 64 + nt * 8 + 2 * qid + 1] = csum[nt][1];
        }
    }
    __syncthreads();

    if (tid < 128) {
        float rs = rbuf[tid] + rbuf[128 + tid];
        g_part[(((size_t)b * 8 + bi) * 8 + bj) * 128 + tid] = rs;
    } else if (offdiag) {
        int t = tid - 128;
        float cs = cbuf[t] + cbuf[128 + t] + cbuf[256 + t] + cbuf[384 + t];
        g_part[(((size_t)b * 8 + bj) * 8 + bi) * 128 + t] = cs;
    }
}

// ---------------------------------------------------------------------------
// K2: row means + total mean. grid=B, block=1024.
// ---------------------------------------------------------------------------
__global__ void means_kernel() {
    int b = blockIdx.x;
    int i = threadIdx.x;
    int ti = i >> 7;
    int ii = i & 127;
    float s = 0.f;
    #pragma unroll
    for (int tj = 0; tj < 8; tj++)
        s += g_part[(((size_t)b * 8 + ti) * 8 + tj) * 128 + ii];
    float m = s * (1.f / DIM);
    g_mean[b * DIM + i] = m;

    __shared__ float sh[32];
    float t = m;
    #pragma unroll
    for (int off = 16; off > 0; off >>= 1)
        t += __shfl_down_sync(0xFFFFFFFFu, t, off);
    if ((i & 31) == 0) sh[i >> 5] = t;
    __syncthreads();
    if (i < 32) {
        float u = sh[i];
        #pragma unroll
        for (int off = 16; off > 0; off >>= 1)
            u += __shfl_down_sync(0xFFFFFFFFu, u, off);
        if (i == 0) g_tot[b] = u * (1.f / DIM);
    }
}

// ---------------------------------------------------------------------------
// K3: warp-per-row triu. All loads/stores lane-contiguous.
// ---------------------------------------------------------------------------
__device__ __forceinline__ long long triu_off(int i) {
    return (long long)i * (2 * DIM + 1 - i) / 2;
}

__global__ void triu_rows_kernel(float* __restrict__ out) {
    int b = blockIdx.y;
    int i = blockIdx.x * 8 + (threadIdx.x >> 5);
    int lane = threadIdx.x & 31;
    const float* row  = g_dcov + ((size_t)b * DIM + i) * DIM;
    const float* mean = g_mean + b * DIM;
    float adj = g_tot[b] - mean[i];
    long long base = (long long)b * OUT_PER_B + triu_off(i) - i;
    for (int j = i + lane; j < DIM; j += 32)
        out[base + j] = row[j] - mean[j] + adj;
}

// ---------------------------------------------------------------------------
extern "C" void kernel_launch(void* const* d_in, const int* in_sizes, int n_in,
                              void* d_out, int out_size) {
    const float* x = (const float*)d_in[0];
    float* out = (float*)d_out;

    static bool attr_set = false;
    if (!attr_set) {
        cudaFuncSetAttribute(syrk_dcov_mma,
                             cudaFuncAttributeMaxDynamicSharedMemorySize, SMEM_BYTES);
        attr_set = true;
    }

    syrk_dcov_mma<<<dim3(NPAIRS, B), 256, SMEM_BYTES>>>(x);
    means_kernel<<<B, 1024>>>();
    triu_rows_kernel<<<dim3(DIM / 8, B), 256>>>(out);
}